// round 1
// baseline (speedup 1.0000x reference)
#include <cuda_runtime.h>
#include <math.h>

#define SEQ 2048
#define DM  1024
#define NH  16
#define DH  64

// ---------------- scratch (device globals; no allocations allowed) ----------
__device__ float g_relenc[SEQ * DM];
__device__ float g_qu[SEQ * DM];       // q + u_param
__device__ float g_qv[SEQ * DM];       // q + v_param
__device__ float g_k[SEQ * DM];
__device__ float g_v[SEQ * DM];
__device__ float g_qr[SEQ * DM];       // rel_enc @ Wkr^T
__device__ float g_bdhat[(size_t)NH * SEQ * SEQ];   // 256 MB scratch
__device__ float g_out1[SEQ * DM];     // attention output before Wf
__device__ int   g_headmax[NH];

// ---------------- relative positional encoding ------------------------------
__global__ void relenc_kernel() {
    int idx = blockIdx.x * blockDim.x + threadIdx.x;
    if (idx >= SEQ * DM) return;
    int f = idx / DM, c = idx % DM;
    int p = SEQ - 1 - f;                       // rel_enc = pe[::-1]
    double e   = (double)(c & ~1) / (double)DM;
    double dv  = pow(10000.0, -e);
    double ang = (double)p * dv;
    g_relenc[idx] = (float)((c & 1) ? cos(ang) : sin(ang));
}

// ---------------- generic tiled GEMM ----------------------------------------
// C = alpha * A @ op(B), optionally batched via blockIdx.z strides.
// transB=1: B is (N,K) row-major (C = A @ B^T). transB=0: B is (K,N).
// epi: 0 = plain, 1 = exact GELU, 2 = dual-bias (C=acc+bias1, C2=acc+bias2)
#define BM 128
#define BN 64
#define BK 16

__global__ __launch_bounds__(256) void gemm_kernel(
    const float* __restrict__ A, int lda, long sA,
    const float* __restrict__ B, int ldb, long sB, int transB,
    float* __restrict__ C, int ldc, long sC,
    int M, int N, int K, float alpha, int epi,
    const float* __restrict__ bias1, const float* __restrict__ bias2,
    float* __restrict__ C2)
{
    __shared__ float As[BK][BM + 4];
    __shared__ float Bs[BK][BN + 4];

    A += (long)blockIdx.z * sA;
    B += (long)blockIdx.z * sB;
    C += (long)blockIdx.z * sC;
    float* Cb2 = C2 ? C2 + (long)blockIdx.z * sC : (float*)0;

    int tid = threadIdx.x;
    int tx = tid & 15;        // 16 column groups of 4
    int ty = tid >> 4;        // 16 row groups of 8
    int m0 = blockIdx.y * BM;
    int n0 = blockIdx.x * BN;

    float acc[8][4];
#pragma unroll
    for (int i = 0; i < 8; i++)
#pragma unroll
        for (int j = 0; j < 4; j++) acc[i][j] = 0.0f;

    for (int k0 = 0; k0 < K; k0 += BK) {
        // A tile: BM x BK = 2048 elems, 8 per thread
#pragma unroll
        for (int i = 0; i < 8; i++) {
            int idx = tid + i * 256;
            int m = idx >> 4, k = idx & 15;
            As[k][m] = A[(long)(m0 + m) * lda + k0 + k];
        }
        if (transB) {
            // B tile: BN x BK = 1024 elems
#pragma unroll
            for (int i = 0; i < 4; i++) {
                int idx = tid + i * 256;
                int n = idx >> 4, k = idx & 15;
                Bs[k][n] = B[(long)(n0 + n) * ldb + k0 + k];
            }
        } else {
            // B tile: BK x BN = 1024 elems
#pragma unroll
            for (int i = 0; i < 4; i++) {
                int idx = tid + i * 256;
                int k = idx >> 6, n = idx & 63;
                Bs[k][n] = B[(long)(k0 + k) * ldb + n0 + n];
            }
        }
        __syncthreads();

#pragma unroll
        for (int kk = 0; kk < BK; kk++) {
            float4 a0 = *(const float4*)&As[kk][ty * 8];
            float4 a1 = *(const float4*)&As[kk][ty * 8 + 4];
            float4 b0 = *(const float4*)&Bs[kk][tx * 4];
            float a[8] = {a0.x, a0.y, a0.z, a0.w, a1.x, a1.y, a1.z, a1.w};
            float b[4] = {b0.x, b0.y, b0.z, b0.w};
#pragma unroll
            for (int i = 0; i < 8; i++)
#pragma unroll
                for (int j = 0; j < 4; j++)
                    acc[i][j] += a[i] * b[j];
        }
        __syncthreads();
    }

#pragma unroll
    for (int i = 0; i < 8; i++) {
        int m = m0 + ty * 8 + i;
#pragma unroll
        for (int j = 0; j < 4; j++) {
            int n = n0 + tx * 4 + j;
            long off = (long)m * ldc + n;
            float x = acc[i][j] * alpha;
            if (epi == 0) {
                C[off] = x;
            } else if (epi == 1) {
                C[off] = 0.5f * x * (1.0f + erff(x * 0.70710678118654752440f));
            } else {
                C[off]   = x + bias1[n];
                Cb2[off] = x + bias2[n];
            }
        }
    }
}

// ---------------- rel-shift combine: w += shift(bdhat) + mask ---------------
__global__ void combine_kernel(float* __restrict__ w, const float* __restrict__ mask) {
    int j = blockIdx.x * 256 + threadIdx.x;
    int s = blockIdx.y;
    int h = blockIdx.z;
    long flat = (long)s * SEQ + j + (SEQ - 1);
    int sp = (int)(flat / (SEQ + 1));
    int jp = (int)(flat - (long)sp * (SEQ + 1));
    float add = (jp == SEQ) ? 0.0f : g_bdhat[((long)h * SEQ + sp) * SEQ + jp];
    long off = ((long)h * SEQ + s) * SEQ + j;
    w[off] += add + mask[(long)s * SEQ + j];
}

// ---------------- softmax (row of 2048) + per-head max weight ---------------
__global__ void init_headmax_kernel() {
    if (threadIdx.x < NH) g_headmax[threadIdx.x] = 0;   // 0 == 0.0f; weights>0
}

__global__ __launch_bounds__(256) void softmax_kernel(float* __restrict__ w) {
    int s = blockIdx.x, h = blockIdx.y;
    float* row = w + ((long)h * SEQ + s) * SEQ;
    __shared__ float red[256];
    int tid = threadIdx.x;

    float vals[8];
    float vmax = -3.0e38f;
#pragma unroll
    for (int i = 0; i < 8; i++) {
        vals[i] = row[tid + i * 256];
        vmax = fmaxf(vmax, vals[i]);
    }
    red[tid] = vmax; __syncthreads();
    for (int st = 128; st > 0; st >>= 1) {
        if (tid < st) red[tid] = fmaxf(red[tid], red[tid + st]);
        __syncthreads();
    }
    vmax = red[0]; __syncthreads();

    float sum = 0.0f;
#pragma unroll
    for (int i = 0; i < 8; i++) {
        vals[i] = expf(vals[i] - vmax);
        sum += vals[i];
    }
    red[tid] = sum; __syncthreads();
    for (int st = 128; st > 0; st >>= 1) {
        if (tid < st) red[tid] += red[tid + st];
        __syncthreads();
    }
    sum = red[0];

    float inv = 1.0f / sum;
#pragma unroll
    for (int i = 0; i < 8; i++)
        row[tid + i * 256] = vals[i] * inv;

    // max weight in a softmax row is exp(0)/sum = inv
    if (tid == 0)
        atomicMax(&g_headmax[h], __float_as_int(inv));
}

__global__ void loss_kernel(float* __restrict__ out) {
    if (threadIdx.x == 0) {
        float s = 0.0f;
        for (int h = 0; h < NH; h++) s += __int_as_float(g_headmax[h]);
        out[(long)SEQ * DM + (long)NH * SEQ * SEQ] = s / (float)NH;
    }
}

// ---------------- launcher ---------------------------------------------------
extern "C" void kernel_launch(void* const* d_in, const int* in_sizes, int n_in,
                              void* d_out, int out_size) {
    (void)in_sizes; (void)n_in; (void)out_size;
    const float* query = (const float*)d_in[0];
    const float* key   = (const float*)d_in[1];
    const float* value = (const float*)d_in[2];
    const float* mask  = (const float*)d_in[3];
    const float* Wq    = (const float*)d_in[4];
    const float* Wke   = (const float*)d_in[5];
    const float* Wkr   = (const float*)d_in[6];
    const float* Wv    = (const float*)d_in[7];
    const float* Wf    = (const float*)d_in[8];
    const float* up    = (const float*)d_in[9];
    const float* vp    = (const float*)d_in[10];

    float* out = (float*)d_out;
    float* w   = out + (long)SEQ * DM;          // weights region of output

    float *relenc, *qu, *qv, *kk, *vv, *qr, *bdhat, *out1;
    cudaGetSymbolAddress((void**)&relenc, g_relenc);
    cudaGetSymbolAddress((void**)&qu,     g_qu);
    cudaGetSymbolAddress((void**)&qv,     g_qv);
    cudaGetSymbolAddress((void**)&kk,     g_k);
    cudaGetSymbolAddress((void**)&vv,     g_v);
    cudaGetSymbolAddress((void**)&qr,     g_qr);
    cudaGetSymbolAddress((void**)&bdhat,  g_bdhat);
    cudaGetSymbolAddress((void**)&out1,   g_out1);

    const float inv_sqrt_dk = 1.0f / 32.0f;     // 1/sqrt(D_MODEL)

    // 1. relative positional encoding
    relenc_kernel<<<(SEQ * DM + 255) / 256, 256>>>();

    // 2. projections (M=2048, N=1024, K=1024)
    dim3 gproj(DM / BN, SEQ / BM, 1);
    // q: dual output qu = q+u, qv = q+v
    gemm_kernel<<<gproj, 256>>>(query, DM, 0, Wq, DM, 0, 1, qu, DM, 0,
                                SEQ, DM, DM, 1.0f, 2, up, vp, qv);
    gemm_kernel<<<gproj, 256>>>(key, DM, 0, Wke, DM, 0, 1, kk, DM, 0,
                                SEQ, DM, DM, 1.0f, 0, 0, 0, 0);
    gemm_kernel<<<gproj, 256>>>(value, DM, 0, Wv, DM, 0, 1, vv, DM, 0,
                                SEQ, DM, DM, 1.0f, 0, 0, 0, 0);
    gemm_kernel<<<gproj, 256>>>(relenc, DM, 0, Wkr, DM, 0, 1, qr, DM, 0,
                                SEQ, DM, DM, 1.0f, 0, 0, 0, 0);

    // 3. A_C (into weights buffer, pre-scaled) and B_D_hat (scratch), batched over heads
    dim3 ghead(SEQ / BN, SEQ / BM, NH);
    gemm_kernel<<<ghead, 256>>>(qu, DM, DH, kk, DM, DH, 1,
                                w, SEQ, (long)SEQ * SEQ,
                                SEQ, SEQ, DH, inv_sqrt_dk, 0, 0, 0, 0);
    gemm_kernel<<<ghead, 256>>>(qv, DM, DH, qr, DM, DH, 1,
                                bdhat, SEQ, (long)SEQ * SEQ,
                                SEQ, SEQ, DH, inv_sqrt_dk, 0, 0, 0, 0);

    // 4. rel-shift combine + mask
    combine_kernel<<<dim3(SEQ / 256, SEQ, NH), 256>>>(w, mask);

    // 5. softmax + per-head max weight
    init_headmax_kernel<<<1, 32>>>();
    softmax_kernel<<<dim3(SEQ, NH), 256>>>(w);

    // 6. out1[s, h*64+d] = sum_f w[h,s,f] * v[f, h*64+d]   (NN, batched)
    dim3 geins(1, SEQ / BM, NH);
    gemm_kernel<<<geins, 256>>>(w, SEQ, (long)SEQ * SEQ, vv, DM, DH, 0,
                                out1, DM, DH,
                                SEQ, DH, SEQ, 1.0f, 0, 0, 0, 0);

    // 7. final projection + exact GELU -> out
    gemm_kernel<<<gproj, 256>>>(out1, DM, 0, Wf, DM, 0, 1, out, DM, 0,
                                SEQ, DM, DM, 1.0f, 1, 0, 0, 0);

    // 8. attention loss scalar
    loss_kernel<<<1, 1>>>(out);
}

// round 3
// speedup vs baseline: 1.6292x; 1.6292x over previous
#include <cuda_runtime.h>
#include <cuda_bf16.h>
#include <math.h>
#include <stdint.h>

#define SEQ 2048
#define DM  1024
#define NH  16
#define DH  64

// ---------------- scratch (device globals; no allocations allowed) ----------
__device__ float g_bdhat[(size_t)NH * SEQ * SEQ];           // 256 MB

__device__ __nv_bfloat16 g_xq_hi[SEQ * DM], g_xq_lo[SEQ * DM];
__device__ __nv_bfloat16 g_xk_hi[SEQ * DM], g_xk_lo[SEQ * DM];
__device__ __nv_bfloat16 g_xv_hi[SEQ * DM], g_xv_lo[SEQ * DM];
__device__ __nv_bfloat16 g_re_hi[SEQ * DM], g_re_lo[SEQ * DM];

__device__ __nv_bfloat16 g_wq_hi[DM * DM],  g_wq_lo[DM * DM];
__device__ __nv_bfloat16 g_wke_hi[DM * DM], g_wke_lo[DM * DM];
__device__ __nv_bfloat16 g_wkr_hi[DM * DM], g_wkr_lo[DM * DM];
__device__ __nv_bfloat16 g_wv_hi[DM * DM],  g_wv_lo[DM * DM];
__device__ __nv_bfloat16 g_wf_hi[DM * DM],  g_wf_lo[DM * DM];

__device__ __nv_bfloat16 g_qu_hi[SEQ * DM], g_qu_lo[SEQ * DM];
__device__ __nv_bfloat16 g_qv_hi[SEQ * DM], g_qv_lo[SEQ * DM];
__device__ __nv_bfloat16 g_k_hi[SEQ * DM],  g_k_lo[SEQ * DM];
__device__ __nv_bfloat16 g_qr_hi[SEQ * DM], g_qr_lo[SEQ * DM];
__device__ __nv_bfloat16 g_vT_hi[DM * SEQ], g_vT_lo[DM * SEQ];   // [n=h*64+d][f]

__device__ __nv_bfloat16 g_w_hi[(size_t)NH * SEQ * SEQ];    // 128 MB
__device__ __nv_bfloat16 g_w_lo[(size_t)NH * SEQ * SEQ];    // 128 MB

__device__ __nv_bfloat16 g_o1_hi[SEQ * DM], g_o1_lo[SEQ * DM];

__device__ int g_headmax[NH];

// ---------------- helpers ----------------------------------------------------
__device__ __forceinline__ uint32_t smem_u32(const void* p) {
    uint32_t a;
    asm("{ .reg .u64 t; cvta.to.shared.u64 t, %1; cvt.u32.u64 %0, t; }" : "=r"(a) : "l"(p));
    return a;
}
__device__ __forceinline__ void cp16(uint32_t s, const void* g) {
    asm volatile("cp.async.cg.shared.global [%0], [%1], 16;" :: "r"(s), "l"(g));
}
__device__ __forceinline__ void cp_commit() {
    asm volatile("cp.async.commit_group;" ::: "memory");
}
template <int N>
__device__ __forceinline__ void cp_wait() {
    asm volatile("cp.async.wait_group %0;" :: "n"(N) : "memory");
}
__device__ __forceinline__ void ldmx4(uint32_t* r, uint32_t addr) {
    asm volatile("ldmatrix.sync.aligned.m8n8.x4.shared.b16 {%0,%1,%2,%3}, [%4];"
                 : "=r"(r[0]), "=r"(r[1]), "=r"(r[2]), "=r"(r[3]) : "r"(addr));
}
__device__ __forceinline__ void mma_bf16(float* c, const uint32_t* a, uint32_t b0, uint32_t b1) {
    asm volatile("mma.sync.aligned.m16n8k16.row.col.f32.bf16.bf16.f32 "
                 "{%0,%1,%2,%3}, {%4,%5,%6,%7}, {%8,%9}, {%0,%1,%2,%3};"
                 : "+f"(c[0]), "+f"(c[1]), "+f"(c[2]), "+f"(c[3])
                 : "r"(a[0]), "r"(a[1]), "r"(a[2]), "r"(a[3]), "r"(b0), "r"(b1));
}
__device__ __forceinline__ void split2(float x, __nv_bfloat16& h, __nv_bfloat16& l) {
    h = __float2bfloat16(x);
    l = __float2bfloat16(x - __bfloat162float(h));
}

// ---------------- elementwise split -----------------------------------------
__global__ void split_kernel(const float* __restrict__ in,
                             __nv_bfloat16* __restrict__ hi,
                             __nv_bfloat16* __restrict__ lo, int n) {
    int i = blockIdx.x * 256 + threadIdx.x;
    if (i < n) split2(in[i], hi[i], lo[i]);
}

// ---------------- relative positional encoding (split output) ---------------
__global__ void relenc_kernel() {
    int idx = blockIdx.x * blockDim.x + threadIdx.x;
    if (idx >= SEQ * DM) return;
    int f = idx / DM, c = idx % DM;
    int p = SEQ - 1 - f;
    double e   = (double)(c & ~1) / (double)DM;
    double dv  = pow(10000.0, -e);
    double ang = (double)p * dv;
    float v = (float)((c & 1) ? cos(ang) : sin(ang));
    split2(v, g_re_hi[idx], g_re_lo[idx]);
}

// ---------------- split-bf16 HMMA GEMM ---------------------------------------
// C = alpha * A @ B^T per batch z. A: M x K, B: N x K (both hi/lo bf16).
// Block 128 x BN, 256 threads (8 warps, 4x2), warp tile 32 x (BN/2), BK=32.
#define EPI_F32    0
#define EPI_GELU   1
#define EPI_SPLIT  2
#define EPI_SPLITT 3
#define EPI_DUAL   4

// smem row stride: 40 bf16 = 80 bytes (bank-conflict-free for ldmatrix)
#define RS 80

template <int BN>
__global__ __launch_bounds__(256) void hmma_gemm(
    const __nv_bfloat16* __restrict__ Ahi, const __nv_bfloat16* __restrict__ Alo,
    int lda, long sA,
    const __nv_bfloat16* __restrict__ Bhi, const __nv_bfloat16* __restrict__ Blo,
    int ldb, long sB,
    int K, float alpha, int epi,
    float* __restrict__ C, int ldc, long sC,
    __nv_bfloat16* __restrict__ O1h, __nv_bfloat16* __restrict__ O1l,
    __nv_bfloat16* __restrict__ O2h, __nv_bfloat16* __restrict__ O2l,
    int ldo, long sO,
    const float* __restrict__ bias1, const float* __restrict__ bias2)
{
    constexpr int WN   = BN / 2;        // warp tile n
    constexpr int NJ   = WN / 8;        // n8 tiles per warp
    constexpr int NH32 = WN / 32;       // n32 halves per warp
    constexpr int A_BYTES = 128 * RS;   // per hi or lo
    constexpr int B_BYTES = BN * RS;
    constexpr int STAGE   = 2 * A_BYTES + 2 * B_BYTES;

    extern __shared__ char smem[];
    uint32_t sb = smem_u32(smem);

    int tid  = threadIdx.x;
    int lane = tid & 31;
    int w    = tid >> 5;
    int wm   = w >> 1;                  // 0..3
    int wn   = w & 1;                   // 0..1
    int m0   = blockIdx.y * 128;
    int n0   = blockIdx.x * BN;
    long z   = blockIdx.z;

    Ahi += z * sA; Alo += z * sA;
    Bhi += z * sB; Blo += z * sB;

    float acc[2][NJ][4];
#pragma unroll
    for (int mi = 0; mi < 2; mi++)
#pragma unroll
        for (int nj = 0; nj < NJ; nj++)
#pragma unroll
            for (int q = 0; q < 4; q++) acc[mi][nj][q] = 0.0f;

    const int nc = K >> 5;              // chunks of 32

    // ---- stage loader ----
    auto load_stage = [&](int st, int k0) {
        uint32_t s0 = sb + st * STAGE;
#pragma unroll
        for (int i = 0; i < 2; i++) {   // A: 128 rows x 4 vec, hi+lo
            int idx = tid + i * 256;
            int r = idx >> 2, v = idx & 3;
            uint32_t so = (uint32_t)(r * RS + v * 16);
            cp16(s0 + so,            Ahi + (long)(m0 + r) * lda + k0 + v * 8);
            cp16(s0 + A_BYTES + so,  Alo + (long)(m0 + r) * lda + k0 + v * 8);
        }
#pragma unroll
        for (int i = 0; i < BN / 64; i++) {  // B: BN rows x 4 vec, hi+lo
            int idx = tid + i * 256;
            int r = idx >> 2, v = idx & 3;
            uint32_t so = (uint32_t)(r * RS + v * 16);
            cp16(s0 + 2 * A_BYTES + so,            Bhi + (long)(n0 + r) * ldb + k0 + v * 8);
            cp16(s0 + 2 * A_BYTES + B_BYTES + so,  Blo + (long)(n0 + r) * ldb + k0 + v * 8);
        }
        cp_commit();
    };

    // ---- compute one staged chunk ----
    auto compute_stage = [&](int st) {
        uint32_t aB = sb + st * STAGE;
        uint32_t bB = aB + 2 * A_BYTES;
        uint32_t l15 = (uint32_t)(lane & 15);
        uint32_t lh  = (uint32_t)(lane >> 4);
#pragma unroll
        for (int ks = 0; ks < 2; ks++) {
            uint32_t a_hi[2][4], a_lo[2][4];
#pragma unroll
            for (int mi = 0; mi < 2; mi++) {
                uint32_t ad = aB + (wm * 32 + mi * 16 + l15) * RS + ks * 32 + lh * 16;
                ldmx4(a_hi[mi], ad);
                ldmx4(a_lo[mi], ad + A_BYTES);
            }
#pragma unroll
            for (int nh = 0; nh < NH32; nh++) {
                uint32_t b_hi[2][4], b_lo[2][4];
#pragma unroll
                for (int nt = 0; nt < 2; nt++) {
                    uint32_t bd = bB + (wn * WN + nh * 32 + nt * 16 + l15) * RS + ks * 32 + lh * 16;
                    ldmx4(b_hi[nt], bd);
                    ldmx4(b_lo[nt], bd + B_BYTES);
                }
#pragma unroll
                for (int mi = 0; mi < 2; mi++)
#pragma unroll
                    for (int nt = 0; nt < 2; nt++)
#pragma unroll
                        for (int s = 0; s < 2; s++) {
                            int nj = nh * 4 + nt * 2 + s;
                            mma_bf16(acc[mi][nj], a_hi[mi], b_hi[nt][s], b_hi[nt][s + 2]);
                            mma_bf16(acc[mi][nj], a_hi[mi], b_lo[nt][s], b_lo[nt][s + 2]);
                            mma_bf16(acc[mi][nj], a_lo[mi], b_hi[nt][s], b_hi[nt][s + 2]);
                        }
            }
        }
    };

    load_stage(0, 0);
    for (int c = 0; c < nc; c++) {
        if (c + 1 < nc) {
            load_stage((c + 1) & 1, (c + 1) << 5);
            cp_wait<1>();
        } else {
            cp_wait<0>();
        }
        __syncthreads();
        compute_stage(c & 1);
        __syncthreads();
    }

    // ---- epilogue ----
    int rb = m0 + wm * 32 + (lane >> 2);
    int cb = n0 + wn * WN + (lane & 3) * 2;
#pragma unroll
    for (int mi = 0; mi < 2; mi++)
#pragma unroll
        for (int nj = 0; nj < NJ; nj++) {
#pragma unroll
            for (int q = 0; q < 4; q++) {
                int m = rb + mi * 16 + (q >> 1) * 8;
                int n = cb + nj * 8 + (q & 1);
                float x = acc[mi][nj][q] * alpha;
                if (epi == EPI_F32) {
                    C[z * sC + (long)m * ldc + n] = x;
                } else if (epi == EPI_GELU) {
                    C[z * sC + (long)m * ldc + n] =
                        0.5f * x * (1.0f + erff(x * 0.70710678118654752440f));
                } else if (epi == EPI_SPLIT) {
                    __nv_bfloat16 h, l; split2(x, h, l);
                    long o = z * sO + (long)m * ldo + n;
                    O1h[o] = h; O1l[o] = l;
                } else if (epi == EPI_SPLITT) {
                    __nv_bfloat16 h, l; split2(x, h, l);
                    long o = z * sO + (long)n * ldo + m;
                    O1h[o] = h; O1l[o] = l;
                } else {  // EPI_DUAL
                    long o = z * sO + (long)m * ldo + n;
                    __nv_bfloat16 h, l;
                    split2(x + bias1[n], h, l); O1h[o] = h; O1l[o] = l;
                    split2(x + bias2[n], h, l); O2h[o] = h; O2l[o] = l;
                }
            }
        }
}

// ---------------- fused combine + softmax + split ----------------------------
__global__ void init_headmax_kernel() {
    if (threadIdx.x < NH) g_headmax[threadIdx.x] = 0;
}

__global__ __launch_bounds__(256) void softmax_kernel(float* __restrict__ w,
                                                      const float* __restrict__ mask) {
    int s = blockIdx.x, h = blockIdx.y;
    long base = ((long)h * SEQ + s) * SEQ;
    __shared__ float red[256];
    int tid = threadIdx.x;

    float vals[8];
    float vmax = -3.0e38f;
#pragma unroll
    for (int i = 0; i < 8; i++) {
        int j = tid + i * 256;
        long flat = (long)s * SEQ + j + (SEQ - 1);
        int sp = (int)(flat / (SEQ + 1));
        int jp = (int)(flat - (long)sp * (SEQ + 1));
        float bd = (jp == SEQ) ? 0.0f : g_bdhat[((long)h * SEQ + sp) * SEQ + jp];
        vals[i] = w[base + j] + bd + mask[(long)s * SEQ + j];
        vmax = fmaxf(vmax, vals[i]);
    }
    red[tid] = vmax; __syncthreads();
    for (int st = 128; st > 0; st >>= 1) {
        if (tid < st) red[tid] = fmaxf(red[tid], red[tid + st]);
        __syncthreads();
    }
    vmax = red[0]; __syncthreads();

    float sum = 0.0f;
#pragma unroll
    for (int i = 0; i < 8; i++) {
        vals[i] = expf(vals[i] - vmax);
        sum += vals[i];
    }
    red[tid] = sum; __syncthreads();
    for (int st = 128; st > 0; st >>= 1) {
        if (tid < st) red[tid] += red[tid + st];
        __syncthreads();
    }
    sum = red[0];
    float inv = 1.0f / sum;

#pragma unroll
    for (int i = 0; i < 8; i++) {
        int j = tid + i * 256;
        float v = vals[i] * inv;
        w[base + j] = v;
        __nv_bfloat16 hh, ll; split2(v, hh, ll);
        g_w_hi[base + j] = hh;
        g_w_lo[base + j] = ll;
    }
    if (tid == 0) atomicMax(&g_headmax[h], __float_as_int(inv));
}

__global__ void loss_kernel(float* __restrict__ out) {
    if (threadIdx.x == 0) {
        float s = 0.0f;
        for (int h = 0; h < NH; h++) s += __int_as_float(g_headmax[h]);
        out[(long)SEQ * DM + (long)NH * SEQ * SEQ] = s / (float)NH;
    }
}

// ---------------- launcher ---------------------------------------------------
extern "C" void kernel_launch(void* const* d_in, const int* in_sizes, int n_in,
                              void* d_out, int out_size) {
    (void)in_sizes; (void)n_in; (void)out_size;
    const float* query = (const float*)d_in[0];
    const float* key   = (const float*)d_in[1];
    const float* value = (const float*)d_in[2];
    const float* mask  = (const float*)d_in[3];
    const float* Wq    = (const float*)d_in[4];
    const float* Wke   = (const float*)d_in[5];
    const float* Wkr   = (const float*)d_in[6];
    const float* Wv    = (const float*)d_in[7];
    const float* Wf    = (const float*)d_in[8];
    const float* up    = (const float*)d_in[9];
    const float* vp    = (const float*)d_in[10];

    float* out = (float*)d_out;
    float* w   = out + (long)SEQ * DM;

    float* bdhat; cudaGetSymbolAddress((void**)&bdhat, g_bdhat);
    __nv_bfloat16 *xqh, *xql, *xkh, *xkl, *xvh, *xvl, *reh, *rel;
    __nv_bfloat16 *wqh, *wql, *wkeh, *wkel, *wkrh, *wkrl, *wvh, *wvl, *wfh, *wfl;
    __nv_bfloat16 *quh, *qul, *qvh, *qvl, *kh, *kl, *qrh, *qrl, *vth, *vtl;
    __nv_bfloat16 *whi, *wlo, *o1h, *o1l;
    cudaGetSymbolAddress((void**)&xqh, g_xq_hi); cudaGetSymbolAddress((void**)&xql, g_xq_lo);
    cudaGetSymbolAddress((void**)&xkh, g_xk_hi); cudaGetSymbolAddress((void**)&xkl, g_xk_lo);
    cudaGetSymbolAddress((void**)&xvh, g_xv_hi); cudaGetSymbolAddress((void**)&xvl, g_xv_lo);
    cudaGetSymbolAddress((void**)&reh, g_re_hi); cudaGetSymbolAddress((void**)&rel, g_re_lo);
    cudaGetSymbolAddress((void**)&wqh, g_wq_hi); cudaGetSymbolAddress((void**)&wql, g_wq_lo);
    cudaGetSymbolAddress((void**)&wkeh, g_wke_hi); cudaGetSymbolAddress((void**)&wkel, g_wke_lo);
    cudaGetSymbolAddress((void**)&wkrh, g_wkr_hi); cudaGetSymbolAddress((void**)&wkrl, g_wkr_lo);
    cudaGetSymbolAddress((void**)&wvh, g_wv_hi); cudaGetSymbolAddress((void**)&wvl, g_wv_lo);
    cudaGetSymbolAddress((void**)&wfh, g_wf_hi); cudaGetSymbolAddress((void**)&wfl, g_wf_lo);
    cudaGetSymbolAddress((void**)&quh, g_qu_hi); cudaGetSymbolAddress((void**)&qul, g_qu_lo);
    cudaGetSymbolAddress((void**)&qvh, g_qv_hi); cudaGetSymbolAddress((void**)&qvl, g_qv_lo);
    cudaGetSymbolAddress((void**)&kh, g_k_hi);   cudaGetSymbolAddress((void**)&kl, g_k_lo);
    cudaGetSymbolAddress((void**)&qrh, g_qr_hi); cudaGetSymbolAddress((void**)&qrl, g_qr_lo);
    cudaGetSymbolAddress((void**)&vth, g_vT_hi); cudaGetSymbolAddress((void**)&vtl, g_vT_lo);
    cudaGetSymbolAddress((void**)&whi, g_w_hi);  cudaGetSymbolAddress((void**)&wlo, g_w_lo);
    cudaGetSymbolAddress((void**)&o1h, g_o1_hi); cudaGetSymbolAddress((void**)&o1l, g_o1_lo);

    const float inv_sqrt_dk = 1.0f / 32.0f;

    constexpr int SMEM128 = 2 * (2 * 128 * RS + 2 * 128 * RS);  // 81920
    constexpr int SMEM64  = 2 * (2 * 128 * RS + 2 * 64 * RS);   // 61440
    cudaFuncSetAttribute(hmma_gemm<128>, cudaFuncAttributeMaxDynamicSharedMemorySize, SMEM128);
    cudaFuncSetAttribute(hmma_gemm<64>,  cudaFuncAttributeMaxDynamicSharedMemorySize, SMEM64);

    // 1. inputs -> bf16 hi/lo splits
    relenc_kernel<<<(SEQ * DM + 255) / 256, 256>>>();
    split_kernel<<<(SEQ * DM + 255) / 256, 256>>>(query, xqh, xql, SEQ * DM);
    split_kernel<<<(SEQ * DM + 255) / 256, 256>>>(key,   xkh, xkl, SEQ * DM);
    split_kernel<<<(SEQ * DM + 255) / 256, 256>>>(value, xvh, xvl, SEQ * DM);
    split_kernel<<<(DM * DM + 255) / 256, 256>>>(Wq,  wqh,  wql,  DM * DM);
    split_kernel<<<(DM * DM + 255) / 256, 256>>>(Wke, wkeh, wkel, DM * DM);
    split_kernel<<<(DM * DM + 255) / 256, 256>>>(Wkr, wkrh, wkrl, DM * DM);
    split_kernel<<<(DM * DM + 255) / 256, 256>>>(Wv,  wvh,  wvl,  DM * DM);
    split_kernel<<<(DM * DM + 255) / 256, 256>>>(Wf,  wfh,  wfl,  DM * DM);

    // 2. projections (M=2048, N=1024, K=1024)
    dim3 gproj(DM / 128, SEQ / 128, 1);
    hmma_gemm<128><<<gproj, 256, SMEM128>>>(xqh, xql, DM, 0, wqh, wql, DM, 0,
        DM, 1.0f, EPI_DUAL, nullptr, 0, 0, quh, qul, qvh, qvl, DM, 0, up, vp);
    hmma_gemm<128><<<gproj, 256, SMEM128>>>(xkh, xkl, DM, 0, wkeh, wkel, DM, 0,
        DM, 1.0f, EPI_SPLIT, nullptr, 0, 0, kh, kl, nullptr, nullptr, DM, 0, nullptr, nullptr);
    hmma_gemm<128><<<gproj, 256, SMEM128>>>(xvh, xvl, DM, 0, wvh, wvl, DM, 0,
        DM, 1.0f, EPI_SPLITT, nullptr, 0, 0, vth, vtl, nullptr, nullptr, SEQ, 0, nullptr, nullptr);
    hmma_gemm<128><<<gproj, 256, SMEM128>>>(reh, rel, DM, 0, wkrh, wkrl, DM, 0,
        DM, 1.0f, EPI_SPLIT, nullptr, 0, 0, qrh, qrl, nullptr, nullptr, DM, 0, nullptr, nullptr);

    // 3. scores: A_C -> w (pre-scaled), B_D_hat -> bdhat (per head, K=64)
    dim3 gsc(SEQ / 128, SEQ / 128, NH);
    hmma_gemm<128><<<gsc, 256, SMEM128>>>(quh, qul, DM, DH, kh, kl, DM, DH,
        DH, inv_sqrt_dk, EPI_F32, w, SEQ, (long)SEQ * SEQ,
        nullptr, nullptr, nullptr, nullptr, 0, 0, nullptr, nullptr);
    hmma_gemm<128><<<gsc, 256, SMEM128>>>(qvh, qvl, DM, DH, qrh, qrl, DM, DH,
        DH, inv_sqrt_dk, EPI_F32, bdhat, SEQ, (long)SEQ * SEQ,
        nullptr, nullptr, nullptr, nullptr, 0, 0, nullptr, nullptr);

    // 4. fused rel-shift + mask + softmax + bf16 split (+ per-head max weight)
    init_headmax_kernel<<<1, 32>>>();
    softmax_kernel<<<dim3(SEQ, NH), 256>>>(w, mask);

    // 5. einsum: out1[s, h*64+d] = sum_f w[h,s,f] * vT[h*64+d, f]
    dim3 gein(1, SEQ / 128, NH);
    hmma_gemm<64><<<gein, 256, SMEM64>>>(whi, wlo, SEQ, (long)SEQ * SEQ,
        vth, vtl, SEQ, (long)DH * SEQ,
        SEQ, 1.0f, EPI_SPLIT, nullptr, 0, 0, o1h, o1l, nullptr, nullptr, DM, DH,
        nullptr, nullptr);

    // 6. final projection + exact GELU -> out
    hmma_gemm<128><<<gproj, 256, SMEM128>>>(o1h, o1l, DM, 0, wfh, wfl, DM, 0,
        DM, 1.0f, EPI_GELU, out, DM, 0,
        nullptr, nullptr, nullptr, nullptr, 0, 0, nullptr, nullptr);

    // 7. loss scalar
    loss_kernel<<<1, 1>>>(out);
}

// round 4
// speedup vs baseline: 2.5497x; 1.5650x over previous
#include <cuda_runtime.h>
#include <cuda_bf16.h>
#include <cuda_fp16.h>
#include <math.h>
#include <stdint.h>

#define SEQ 2048
#define DM  1024
#define NH  16
#define DH  64
#define SS  ((long)SEQ * SEQ)

// ---------------- scratch (device globals; no allocations allowed) ----------
__device__ __half g_bds[(size_t)NH * SEQ * SEQ];            // shifted B_D, fp16

__device__ __nv_bfloat16 g_xq_hi[SEQ * DM], g_xq_lo[SEQ * DM];
__device__ __nv_bfloat16 g_xk_hi[SEQ * DM], g_xk_lo[SEQ * DM];
__device__ __nv_bfloat16 g_xv_hi[SEQ * DM], g_xv_lo[SEQ * DM];
__device__ __nv_bfloat16 g_re_hi[SEQ * DM], g_re_lo[SEQ * DM];

__device__ __nv_bfloat16 g_wq_hi[DM * DM],  g_wq_lo[DM * DM];
__device__ __nv_bfloat16 g_wke_hi[DM * DM], g_wke_lo[DM * DM];
__device__ __nv_bfloat16 g_wkr_hi[DM * DM], g_wkr_lo[DM * DM];
__device__ __nv_bfloat16 g_wv_hi[DM * DM],  g_wv_lo[DM * DM];
__device__ __nv_bfloat16 g_wf_hi[DM * DM],  g_wf_lo[DM * DM];

__device__ __nv_bfloat16 g_qu_hi[SEQ * DM], g_qu_lo[SEQ * DM];
__device__ __nv_bfloat16 g_qv_hi[SEQ * DM], g_qv_lo[SEQ * DM];
__device__ __nv_bfloat16 g_k_hi[SEQ * DM],  g_k_lo[SEQ * DM];
__device__ __nv_bfloat16 g_qr_hi[SEQ * DM], g_qr_lo[SEQ * DM];
__device__ __nv_bfloat16 g_vT_hi[DM * SEQ], g_vT_lo[DM * SEQ];   // [h*64+d][f]

__device__ __nv_bfloat16 g_o1_hi[SEQ * DM], g_o1_lo[SEQ * DM];

__device__ int g_headmax[NH];

// ---------------- helpers ----------------------------------------------------
__device__ __forceinline__ uint32_t smem_u32(const void* p) {
    uint32_t a;
    asm("{ .reg .u64 t; cvta.to.shared.u64 t, %1; cvt.u32.u64 %0, t; }" : "=r"(a) : "l"(p));
    return a;
}
__device__ __forceinline__ void cp16(uint32_t s, const void* g) {
    asm volatile("cp.async.cg.shared.global [%0], [%1], 16;" :: "r"(s), "l"(g));
}
__device__ __forceinline__ void cp_commit() {
    asm volatile("cp.async.commit_group;" ::: "memory");
}
template <int N>
__device__ __forceinline__ void cp_wait() {
    asm volatile("cp.async.wait_group %0;" :: "n"(N) : "memory");
}
__device__ __forceinline__ void ldmx4(uint32_t* r, uint32_t addr) {
    asm volatile("ldmatrix.sync.aligned.m8n8.x4.shared.b16 {%0,%1,%2,%3}, [%4];"
                 : "=r"(r[0]), "=r"(r[1]), "=r"(r[2]), "=r"(r[3]) : "r"(addr));
}
__device__ __forceinline__ void mma_bf16(float* c, const uint32_t* a, uint32_t b0, uint32_t b1) {
    asm volatile("mma.sync.aligned.m16n8k16.row.col.f32.bf16.bf16.f32 "
                 "{%0,%1,%2,%3}, {%4,%5,%6,%7}, {%8,%9}, {%0,%1,%2,%3};"
                 : "+f"(c[0]), "+f"(c[1]), "+f"(c[2]), "+f"(c[3])
                 : "r"(a[0]), "r"(a[1]), "r"(a[2]), "r"(a[3]), "r"(b0), "r"(b1));
}
__device__ __forceinline__ void split2(float x, __nv_bfloat16& h, __nv_bfloat16& l) {
    h = __float2bfloat16(x);
    l = __float2bfloat16(x - __bfloat162float(h));
}

struct alignas(16) BF8 { __nv_bfloat16 v[8]; };
struct alignas(8)  BF4 { __nv_bfloat16 v[4]; };

// ---------------- merged elementwise split -----------------------------------
__global__ __launch_bounds__(256) void split_all(
    const float* __restrict__ q, const float* __restrict__ k, const float* __restrict__ v,
    const float* __restrict__ wq, const float* __restrict__ wke, const float* __restrict__ wkr,
    const float* __restrict__ wv, const float* __restrict__ wf)
{
    int z = blockIdx.z;
    long n = (z < 3) ? (long)SEQ * DM : (long)DM * DM;
    long i = ((long)blockIdx.x * 256 + threadIdx.x) * 4;
    if (i >= n) return;
    const float* src; __nv_bfloat16 *dh, *dl;
    switch (z) {
        case 0: src = q;   dh = g_xq_hi; dl = g_xq_lo; break;
        case 1: src = k;   dh = g_xk_hi; dl = g_xk_lo; break;
        case 2: src = v;   dh = g_xv_hi; dl = g_xv_lo; break;
        case 3: src = wq;  dh = g_wq_hi;  dl = g_wq_lo;  break;
        case 4: src = wke; dh = g_wke_hi; dl = g_wke_lo; break;
        case 5: src = wkr; dh = g_wkr_hi; dl = g_wkr_lo; break;
        case 6: src = wv;  dh = g_wv_hi;  dl = g_wv_lo;  break;
        default: src = wf; dh = g_wf_hi;  dl = g_wf_lo;  break;
    }
    float4 x = *(const float4*)(src + i);
    BF4 h, l;
    split2(x.x, h.v[0], l.v[0]); split2(x.y, h.v[1], l.v[1]);
    split2(x.z, h.v[2], l.v[2]); split2(x.w, h.v[3], l.v[3]);
    *(BF4*)(dh + i) = h;
    *(BF4*)(dl + i) = l;
}

// ---------------- relative positional encoding (fp32, split output) ----------
__global__ __launch_bounds__(256) void relenc_kernel() {
    if (blockIdx.x == 0 && threadIdx.x < NH) g_headmax[threadIdx.x] = 0;
    long i = ((long)blockIdx.x * 256 + threadIdx.x) * 4;
    if (i >= (long)SEQ * DM) return;
    int f = (int)(i / DM), c0 = (int)(i % DM);
    float p = (float)(SEQ - 1 - f);
    BF4 h, l;
#pragma unroll
    for (int t = 0; t < 4; t++) {
        int c = c0 + t;
        float e  = (float)(c & ~1) * (1.0f / (float)DM);
        float dv = exp2f(-e * 13.287712379549449f);    // log2(10000)
        float ang = p * dv;
        float s, cs; sincosf(ang, &s, &cs);
        split2((c & 1) ? cs : s, h.v[t], l.v[t]);
    }
    *(BF4*)(g_re_hi + i) = h;
    *(BF4*)(g_re_lo + i) = l;
}

// ---------------- split-bf16 HMMA GEMM core ----------------------------------
// C = alpha * A @ B^T.  A: M x K (hi/lo bf16, or fp32 with in-kernel split),
// B: N x K (hi/lo bf16).  Block 128 x BN, 256 threads, warp tile 32 x BN/2.
#define EPI_F32    0
#define EPI_GELU   1
#define EPI_SPLIT  2
#define EPI_SPLITT 3
#define EPI_DUAL   4
#define EPI_SHIFT  5

#define RS 80            // bf16 smem row stride in bytes (40 bf16)
#define RS32 144         // fp32 staging row stride in bytes

template <int BN, bool AF32>
__device__ __forceinline__ void gemm_core(
    const __nv_bfloat16* __restrict__ Ahi, const __nv_bfloat16* __restrict__ Alo,
    const float* __restrict__ A32, int lda,
    const __nv_bfloat16* __restrict__ Bhi, const __nv_bfloat16* __restrict__ Blo, int ldb,
    int K, float alpha, int epi,
    float* __restrict__ C, int ldc,
    __nv_bfloat16* __restrict__ O1h, __nv_bfloat16* __restrict__ O1l,
    __nv_bfloat16* __restrict__ O2h, __nv_bfloat16* __restrict__ O2l, int ldo,
    const float* __restrict__ b1, const float* __restrict__ b2,
    __half* __restrict__ Csh)
{
    constexpr int WN   = BN / 2;
    constexpr int NJ   = WN / 8;
    constexpr int NH32 = WN / 32;
    constexpr int ABF  = 128 * RS;
    constexpr int A32B = AF32 ? 128 * RS32 : 0;
    constexpr int BB   = BN * RS;
    constexpr int OFF_AHI = A32B;
    constexpr int OFF_ALO = A32B + ABF;
    constexpr int OFF_BHI = A32B + 2 * ABF;
    constexpr int OFF_BLO = A32B + 2 * ABF + BB;
    constexpr int STAGE   = A32B + 2 * ABF + 2 * BB;

    extern __shared__ char smem[];
    uint32_t sb = smem_u32(smem);

    int tid  = threadIdx.x;
    int lane = tid & 31;
    int w    = tid >> 5;
    int wm   = w >> 1;
    int wn   = w & 1;
    int m0   = blockIdx.y * 128;
    int n0   = blockIdx.x * BN;

    float acc[2][NJ][4];
#pragma unroll
    for (int mi = 0; mi < 2; mi++)
#pragma unroll
        for (int nj = 0; nj < NJ; nj++)
#pragma unroll
            for (int q = 0; q < 4; q++) acc[mi][nj][q] = 0.0f;

    const int nc = K >> 5;

    auto load_stage = [&](int st, int k0) {
        uint32_t s0 = sb + st * STAGE;
        if (AF32) {
#pragma unroll
            for (int i = 0; i < 4; i++) {    // 128 rows x 8 vec16 of fp32
                int idx = tid + i * 256;
                int r = idx >> 3, vv = idx & 7;
                cp16(s0 + r * RS32 + vv * 16, A32 + (long)(m0 + r) * lda + k0 + vv * 4);
            }
        } else {
#pragma unroll
            for (int i = 0; i < 2; i++) {    // 128 rows x 4 vec16, hi+lo
                int idx = tid + i * 256;
                int r = idx >> 2, vv = idx & 3;
                uint32_t so = (uint32_t)(r * RS + vv * 16);
                cp16(s0 + OFF_AHI + so, Ahi + (long)(m0 + r) * lda + k0 + vv * 8);
                cp16(s0 + OFF_ALO + so, Alo + (long)(m0 + r) * lda + k0 + vv * 8);
            }
        }
#pragma unroll
        for (int i = 0; i < BN / 64; i++) {
            int idx = tid + i * 256;
            int r = idx >> 2, vv = idx & 3;
            uint32_t so = (uint32_t)(r * RS + vv * 16);
            cp16(s0 + OFF_BHI + so, Bhi + (long)(n0 + r) * ldb + k0 + vv * 8);
            cp16(s0 + OFF_BLO + so, Blo + (long)(n0 + r) * ldb + k0 + vv * 8);
        }
        cp_commit();
    };

    auto convert_stage = [&](int st) {
        char* s0 = smem + st * STAGE;
        int r = tid >> 1, hf = tid & 1;
        float4 f[4];
#pragma unroll
        for (int q = 0; q < 4; q++)
            f[q] = *(const float4*)(s0 + r * RS32 + hf * 64 + q * 16);
        BF8 h0, h1, l0, l1;
#pragma unroll
        for (int q = 0; q < 2; q++) {
            split2(f[q].x, h0.v[q*4+0], l0.v[q*4+0]); split2(f[q].y, h0.v[q*4+1], l0.v[q*4+1]);
            split2(f[q].z, h0.v[q*4+2], l0.v[q*4+2]); split2(f[q].w, h0.v[q*4+3], l0.v[q*4+3]);
        }
#pragma unroll
        for (int q = 2; q < 4; q++) {
            split2(f[q].x, h1.v[(q-2)*4+0], l1.v[(q-2)*4+0]); split2(f[q].y, h1.v[(q-2)*4+1], l1.v[(q-2)*4+1]);
            split2(f[q].z, h1.v[(q-2)*4+2], l1.v[(q-2)*4+2]); split2(f[q].w, h1.v[(q-2)*4+3], l1.v[(q-2)*4+3]);
        }
        char* dh = s0 + OFF_AHI + r * RS + hf * 32;
        char* dl = s0 + OFF_ALO + r * RS + hf * 32;
        *(BF8*)(dh)      = h0; *(BF8*)(dh + 16) = h1;
        *(BF8*)(dl)      = l0; *(BF8*)(dl + 16) = l1;
    };

    auto compute_stage = [&](int st) {
        uint32_t aB = sb + st * STAGE + OFF_AHI;
        uint32_t bB = sb + st * STAGE + OFF_BHI;
        uint32_t l15 = (uint32_t)(lane & 15);
        uint32_t lh  = (uint32_t)(lane >> 4);
#pragma unroll
        for (int ks = 0; ks < 2; ks++) {
            uint32_t a_hi[2][4], a_lo[2][4];
#pragma unroll
            for (int mi = 0; mi < 2; mi++) {
                uint32_t ad = aB + (wm * 32 + mi * 16 + l15) * RS + ks * 32 + lh * 16;
                ldmx4(a_hi[mi], ad);
                ldmx4(a_lo[mi], ad + ABF);
            }
#pragma unroll
            for (int nh = 0; nh < NH32; nh++) {
                uint32_t b_hi[2][4], b_lo[2][4];
#pragma unroll
                for (int nt = 0; nt < 2; nt++) {
                    uint32_t bd = bB + (wn * WN + nh * 32 + nt * 16 + l15) * RS + ks * 32 + lh * 16;
                    ldmx4(b_hi[nt], bd);
                    ldmx4(b_lo[nt], bd + BB);
                }
#pragma unroll
                for (int mi = 0; mi < 2; mi++)
#pragma unroll
                    for (int nt = 0; nt < 2; nt++)
#pragma unroll
                        for (int s = 0; s < 2; s++) {
                            int nj = nh * 4 + nt * 2 + s;
                            mma_bf16(acc[mi][nj], a_hi[mi], b_hi[nt][s], b_hi[nt][s + 2]);
                            mma_bf16(acc[mi][nj], a_hi[mi], b_lo[nt][s], b_lo[nt][s + 2]);
                            mma_bf16(acc[mi][nj], a_lo[mi], b_hi[nt][s], b_hi[nt][s + 2]);
                        }
            }
        }
    };

    load_stage(0, 0);
    for (int c = 0; c < nc; c++) {
        if (c + 1 < nc) {
            load_stage((c + 1) & 1, (c + 1) << 5);
            cp_wait<1>();
        } else {
            cp_wait<0>();
        }
        __syncthreads();
        if (AF32) { convert_stage(c & 1); __syncthreads(); }
        compute_stage(c & 1);
        __syncthreads();
    }

    // ---- epilogue ----
    int rb = m0 + wm * 32 + (lane >> 2);
    int cb = n0 + wn * WN + (lane & 3) * 2;
#pragma unroll
    for (int mi = 0; mi < 2; mi++)
#pragma unroll
        for (int nj = 0; nj < NJ; nj++) {
#pragma unroll
            for (int q = 0; q < 4; q++) {
                int m = rb + mi * 16 + (q >> 1) * 8;
                int n = cb + nj * 8 + (q & 1);
                float x = acc[mi][nj][q] * alpha;
                if (epi == EPI_F32) {
                    C[(long)m * ldc + n] = x;
                } else if (epi == EPI_GELU) {
                    C[(long)m * ldc + n] =
                        0.5f * x * (1.0f + erff(x * 0.70710678118654752440f));
                } else if (epi == EPI_SPLIT) {
                    __nv_bfloat16 h, l; split2(x, h, l);
                    long o = (long)m * ldo + n;
                    O1h[o] = h; O1l[o] = l;
                } else if (epi == EPI_SPLITT) {
                    __nv_bfloat16 h, l; split2(x, h, l);
                    long o = (long)n * ldo + m;
                    O1h[o] = h; O1l[o] = l;
                } else if (epi == EPI_DUAL) {
                    long o = (long)m * ldo + n;
                    __nv_bfloat16 h, l;
                    split2(x + b1[n], h, l); O1h[o] = h; O1l[o] = l;
                    split2(x + b2[n], h, l); O2h[o] = h; O2l[o] = l;
                } else {  // EPI_SHIFT: scatter B_D_hat[sp=m, jp=n] to shifted pos
                    int sp = m, jp = n, s, j;
                    bool ok = true;
                    if (jp >= SEQ - 1 - sp)      { s = sp;     j = jp - (SEQ - 1) + sp; }
                    else if (sp >= 1)            { s = sp - 1; j = jp + sp + 1; }
                    else ok = false;
                    if (ok) Csh[(long)s * SEQ + j] = __float2half(x);
                }
            }
        }
}

// ---------------- GEMM wrapper kernels ---------------------------------------
__global__ __launch_bounds__(256) void proj_all(const float* __restrict__ up,
                                                const float* __restrict__ vp) {
    int z = blockIdx.z;
    if (z == 0)
        gemm_core<128, false>(g_xq_hi, g_xq_lo, nullptr, DM, g_wq_hi, g_wq_lo, DM,
            DM, 1.0f, EPI_DUAL, nullptr, 0, g_qu_hi, g_qu_lo, g_qv_hi, g_qv_lo, DM,
            up, vp, nullptr);
    else if (z == 1)
        gemm_core<128, false>(g_xk_hi, g_xk_lo, nullptr, DM, g_wke_hi, g_wke_lo, DM,
            DM, 1.0f, EPI_SPLIT, nullptr, 0, g_k_hi, g_k_lo, nullptr, nullptr, DM,
            nullptr, nullptr, nullptr);
    else if (z == 2)
        gemm_core<128, false>(g_xv_hi, g_xv_lo, nullptr, DM, g_wv_hi, g_wv_lo, DM,
            DM, 1.0f, EPI_SPLITT, nullptr, 0, g_vT_hi, g_vT_lo, nullptr, nullptr, SEQ,
            nullptr, nullptr, nullptr);
    else
        gemm_core<128, false>(g_re_hi, g_re_lo, nullptr, DM, g_wkr_hi, g_wkr_lo, DM,
            DM, 1.0f, EPI_SPLIT, nullptr, 0, g_qr_hi, g_qr_lo, nullptr, nullptr, DM,
            nullptr, nullptr, nullptr);
}

__global__ __launch_bounds__(256) void score_all(float* __restrict__ w) {
    int zz = blockIdx.z;
    int h = zz & (NH - 1);
    const float alpha = 1.0f / 32.0f;   // 1/sqrt(D_MODEL)
    if (zz < NH)
        gemm_core<128, false>(g_qu_hi + h * DH, g_qu_lo + h * DH, nullptr, DM,
            g_k_hi + h * DH, g_k_lo + h * DH, DM,
            DH, alpha, EPI_F32, w + (long)h * SS, SEQ,
            nullptr, nullptr, nullptr, nullptr, 0, nullptr, nullptr, nullptr);
    else
        gemm_core<128, false>(g_qv_hi + h * DH, g_qv_lo + h * DH, nullptr, DM,
            g_qr_hi + h * DH, g_qr_lo + h * DH, DM,
            DH, alpha, EPI_SHIFT, nullptr, 0,
            nullptr, nullptr, nullptr, nullptr, 0, nullptr, nullptr,
            g_bds + (long)h * SS);
}

__global__ __launch_bounds__(256) void einsum_k(const float* __restrict__ w) {
    int h = blockIdx.z;
    gemm_core<64, true>(nullptr, nullptr, w + (long)h * SS, SEQ,
        g_vT_hi + (long)h * DH * SEQ, g_vT_lo + (long)h * DH * SEQ, SEQ,
        SEQ, 1.0f, EPI_SPLIT, nullptr, 0,
        g_o1_hi + h * DH, g_o1_lo + h * DH, nullptr, nullptr, DM,
        nullptr, nullptr, nullptr);
}

__global__ __launch_bounds__(256) void final_k(float* __restrict__ out) {
    gemm_core<128, false>(g_o1_hi, g_o1_lo, nullptr, DM, g_wf_hi, g_wf_lo, DM,
        DM, 1.0f, EPI_GELU, out, DM,
        nullptr, nullptr, nullptr, nullptr, 0, nullptr, nullptr, nullptr);
}

// ---------------- fused shift-add + softmax ----------------------------------
__global__ __launch_bounds__(256) void softmax_kernel(float* __restrict__ w,
                                                      const float* __restrict__ mask) {
    int s = blockIdx.x, h = blockIdx.y;
    long base = ((long)h * SEQ + s) * SEQ;
    const __half* bds = g_bds + base;
    __shared__ float red[256];
    int tid = threadIdx.x;

    float vals[8];
    float vmax = -3.0e38f;
#pragma unroll
    for (int i = 0; i < 8; i++) {
        int j = tid + i * 256;
        float bd = (j == s + 1) ? 0.0f : __half2float(bds[j]);
        vals[i] = w[base + j] + bd + mask[(long)s * SEQ + j];
        vmax = fmaxf(vmax, vals[i]);
    }
    red[tid] = vmax; __syncthreads();
    for (int st = 128; st > 0; st >>= 1) {
        if (tid < st) red[tid] = fmaxf(red[tid], red[tid + st]);
        __syncthreads();
    }
    vmax = red[0]; __syncthreads();

    float sum = 0.0f;
#pragma unroll
    for (int i = 0; i < 8; i++) {
        vals[i] = expf(vals[i] - vmax);
        sum += vals[i];
    }
    red[tid] = sum; __syncthreads();
    for (int st = 128; st > 0; st >>= 1) {
        if (tid < st) red[tid] += red[tid + st];
        __syncthreads();
    }
    sum = red[0];
    float inv = 1.0f / sum;

#pragma unroll
    for (int i = 0; i < 8; i++)
        w[base + tid + i * 256] = vals[i] * inv;

    if (tid == 0) atomicMax(&g_headmax[h], __float_as_int(inv));
}

__global__ void loss_kernel(float* __restrict__ out) {
    if (threadIdx.x == 0) {
        float s = 0.0f;
        for (int h = 0; h < NH; h++) s += __int_as_float(g_headmax[h]);
        out[(long)SEQ * DM + (long)NH * SS] = s / (float)NH;
    }
}

// ---------------- launcher ---------------------------------------------------
extern "C" void kernel_launch(void* const* d_in, const int* in_sizes, int n_in,
                              void* d_out, int out_size) {
    (void)in_sizes; (void)n_in; (void)out_size;
    const float* query = (const float*)d_in[0];
    const float* key   = (const float*)d_in[1];
    const float* value = (const float*)d_in[2];
    const float* mask  = (const float*)d_in[3];
    const float* Wq    = (const float*)d_in[4];
    const float* Wke   = (const float*)d_in[5];
    const float* Wkr   = (const float*)d_in[6];
    const float* Wv    = (const float*)d_in[7];
    const float* Wf    = (const float*)d_in[8];
    const float* up    = (const float*)d_in[9];
    const float* vp    = (const float*)d_in[10];

    float* out = (float*)d_out;
    float* w   = out + (long)SEQ * DM;

    constexpr int SMEM_BF  = 2 * (2 * 128 * RS + 2 * 128 * RS);                 // 81920
    constexpr int SMEM_E   = 2 * (128 * RS32 + 2 * 128 * RS + 2 * 64 * RS);     // 98304
    cudaFuncSetAttribute(proj_all,  cudaFuncAttributeMaxDynamicSharedMemorySize, SMEM_BF);
    cudaFuncSetAttribute(score_all, cudaFuncAttributeMaxDynamicSharedMemorySize, SMEM_BF);
    cudaFuncSetAttribute(final_k,   cudaFuncAttributeMaxDynamicSharedMemorySize, SMEM_BF);
    cudaFuncSetAttribute(einsum_k,  cudaFuncAttributeMaxDynamicSharedMemorySize, SMEM_E);

    // 1. relenc (+ headmax init) and merged input/weight splits
    relenc_kernel<<<SEQ * DM / 1024, 256>>>();
    split_all<<<dim3(SEQ * DM / 1024, 1, 8), 256>>>(query, key, value, Wq, Wke, Wkr, Wv, Wf);

    // 2. all projections, one launch (z: q-dual, k, vT, rel)
    proj_all<<<dim3(DM / 128, SEQ / 128, 4), 256, SMEM_BF>>>(up, vp);

    // 3. both score GEMMs, one launch (z<16: A_C -> w; z>=16: B_D shifted -> g_bds)
    score_all<<<dim3(SEQ / 128, SEQ / 128, 2 * NH), 256, SMEM_BF>>>(w);

    // 4. fused shift-add + mask + softmax (+ per-head max weight)
    softmax_kernel<<<dim3(SEQ, NH), 256>>>(w, mask);

    // 5. einsum with in-kernel fp32->bf16 split of weights
    einsum_k<<<dim3(1, SEQ / 128, NH), 256, SMEM_E>>>(w);

    // 6. final projection + exact GELU
    final_k<<<dim3(DM / 128, SEQ / 128, 1), 256, SMEM_BF>>>(out);

    // 7. loss scalar
    loss_kernel<<<1, 1>>>(out);
}

// round 6
// speedup vs baseline: 2.7756x; 1.0886x over previous
#include <cuda_runtime.h>
#include <cuda_bf16.h>
#include <cuda_fp16.h>
#include <math.h>
#include <stdint.h>

#define SEQ 2048
#define DM  1024
#define NH  16
#define DH  64
#define SS  ((long)SEQ * SEQ)

// ---------------- scratch (device globals; no allocations allowed) ----------
__device__ __half g_bds[(size_t)NH * SEQ * SEQ];            // shifted B_D, fp16
__device__ __half g_ac[(size_t)NH * SEQ * SEQ];             // A_C scores, fp16

__device__ __nv_bfloat16 g_xq_hi[SEQ * DM], g_xq_lo[SEQ * DM];
__device__ __nv_bfloat16 g_xk_hi[SEQ * DM], g_xk_lo[SEQ * DM];
__device__ __nv_bfloat16 g_xv_hi[SEQ * DM], g_xv_lo[SEQ * DM];
__device__ __nv_bfloat16 g_re_hi[SEQ * DM], g_re_lo[SEQ * DM];

__device__ __nv_bfloat16 g_wq_hi[DM * DM],  g_wq_lo[DM * DM];
__device__ __nv_bfloat16 g_wke_hi[DM * DM], g_wke_lo[DM * DM];
__device__ __nv_bfloat16 g_wkr_hi[DM * DM], g_wkr_lo[DM * DM];
__device__ __nv_bfloat16 g_wv_hi[DM * DM],  g_wv_lo[DM * DM];
__device__ __nv_bfloat16 g_wf_hi[DM * DM],  g_wf_lo[DM * DM];

__device__ __half g_qu16[SEQ * DM], g_qv16[SEQ * DM];       // fp16 score operands
__device__ __half g_k16[SEQ * DM],  g_qr16[SEQ * DM];

__device__ __nv_bfloat16 g_vT_hi[DM * SEQ], g_vT_lo[DM * SEQ];   // [h*64+d][f]
__device__ __nv_bfloat16 g_o1_hi[SEQ * DM], g_o1_lo[SEQ * DM];

__device__ int g_headmax[NH];

// ---------------- helpers ----------------------------------------------------
__device__ __forceinline__ uint32_t smem_u32(const void* p) {
    uint32_t a;
    asm("{ .reg .u64 t; cvta.to.shared.u64 t, %1; cvt.u32.u64 %0, t; }" : "=r"(a) : "l"(p));
    return a;
}
__device__ __forceinline__ void cp16(uint32_t s, const void* g) {
    asm volatile("cp.async.cg.shared.global [%0], [%1], 16;" :: "r"(s), "l"(g));
}
__device__ __forceinline__ void cp_commit() {
    asm volatile("cp.async.commit_group;" ::: "memory");
}
template <int N>
__device__ __forceinline__ void cp_wait() {
    asm volatile("cp.async.wait_group %0;" :: "n"(N) : "memory");
}
__device__ __forceinline__ void ldmx4(uint32_t* r, uint32_t addr) {
    asm volatile("ldmatrix.sync.aligned.m8n8.x4.shared.b16 {%0,%1,%2,%3}, [%4];"
                 : "=r"(r[0]), "=r"(r[1]), "=r"(r[2]), "=r"(r[3]) : "r"(addr));
}
__device__ __forceinline__ void mma_bf16(float* c, const uint32_t* a, uint32_t b0, uint32_t b1) {
    asm volatile("mma.sync.aligned.m16n8k16.row.col.f32.bf16.bf16.f32 "
                 "{%0,%1,%2,%3}, {%4,%5,%6,%7}, {%8,%9}, {%0,%1,%2,%3};"
                 : "+f"(c[0]), "+f"(c[1]), "+f"(c[2]), "+f"(c[3])
                 : "r"(a[0]), "r"(a[1]), "r"(a[2]), "r"(a[3]), "r"(b0), "r"(b1));
}
__device__ __forceinline__ void mma_f16(float* c, const uint32_t* a, uint32_t b0, uint32_t b1) {
    asm volatile("mma.sync.aligned.m16n8k16.row.col.f32.f16.f16.f32 "
                 "{%0,%1,%2,%3}, {%4,%5,%6,%7}, {%8,%9}, {%0,%1,%2,%3};"
                 : "+f"(c[0]), "+f"(c[1]), "+f"(c[2]), "+f"(c[3])
                 : "r"(a[0]), "r"(a[1]), "r"(a[2]), "r"(a[3]), "r"(b0), "r"(b1));
}
__device__ __forceinline__ void split2(float x, __nv_bfloat16& h, __nv_bfloat16& l) {
    h = __float2bfloat16(x);
    l = __float2bfloat16(x - __bfloat162float(h));
}

struct alignas(16) BF8 { __nv_bfloat16 v[8]; };
struct alignas(8)  BF4 { __nv_bfloat16 v[4]; };

// ---------------- merged elementwise split -----------------------------------
__global__ __launch_bounds__(256) void split_all(
    const float* __restrict__ q, const float* __restrict__ k, const float* __restrict__ v,
    const float* __restrict__ wq, const float* __restrict__ wke, const float* __restrict__ wkr,
    const float* __restrict__ wv, const float* __restrict__ wf)
{
    int z = blockIdx.z;
    long n = (z < 3) ? (long)SEQ * DM : (long)DM * DM;
    long i = ((long)blockIdx.x * 256 + threadIdx.x) * 4;
    if (i >= n) return;
    const float* src; __nv_bfloat16 *dh, *dl;
    switch (z) {
        case 0: src = q;   dh = g_xq_hi; dl = g_xq_lo; break;
        case 1: src = k;   dh = g_xk_hi; dl = g_xk_lo; break;
        case 2: src = v;   dh = g_xv_hi; dl = g_xv_lo; break;
        case 3: src = wq;  dh = g_wq_hi;  dl = g_wq_lo;  break;
        case 4: src = wke; dh = g_wke_hi; dl = g_wke_lo; break;
        case 5: src = wkr; dh = g_wkr_hi; dl = g_wkr_lo; break;
        case 6: src = wv;  dh = g_wv_hi;  dl = g_wv_lo;  break;
        default: src = wf; dh = g_wf_hi;  dl = g_wf_lo;  break;
    }
    float4 x = *(const float4*)(src + i);
    BF4 h, l;
    split2(x.x, h.v[0], l.v[0]); split2(x.y, h.v[1], l.v[1]);
    split2(x.z, h.v[2], l.v[2]); split2(x.w, h.v[3], l.v[3]);
    *(BF4*)(dh + i) = h;
    *(BF4*)(dl + i) = l;
}

// ---------------- relative positional encoding (fp32, split output) ----------
__global__ __launch_bounds__(256) void relenc_kernel() {
    if (blockIdx.x == 0 && threadIdx.x < NH) g_headmax[threadIdx.x] = 0;
    long i = ((long)blockIdx.x * 256 + threadIdx.x) * 4;
    if (i >= (long)SEQ * DM) return;
    int f = (int)(i / DM), c0 = (int)(i % DM);
    float p = (float)(SEQ - 1 - f);
    BF4 h, l;
#pragma unroll
    for (int t = 0; t < 4; t++) {
        int c = c0 + t;
        float e  = (float)(c & ~1) * (1.0f / (float)DM);
        float dv = exp2f(-e * 13.287712379549449f);    // log2(10000)
        float ang = p * dv;
        float s, cs; sincosf(ang, &s, &cs);
        split2((c & 1) ? cs : s, h.v[t], l.v[t]);
    }
    *(BF4*)(g_re_hi + i) = h;
    *(BF4*)(g_re_lo + i) = l;
}

// ---------------- split-bf16 HMMA GEMM core (projections/einsum/final) -------
#define EPI_GELU   1
#define EPI_SPLIT  2
#define EPI_SPLITT 3
#define EPI_HALF   6
#define EPI_DUAL16 7

#define RS 80            // bf16 smem row stride in bytes (40 bf16)
#define RS32 144         // fp32 staging row stride in bytes

template <int BN, bool AF32>
__device__ __forceinline__ void gemm_core(
    const __nv_bfloat16* __restrict__ Ahi, const __nv_bfloat16* __restrict__ Alo,
    const float* __restrict__ A32, int lda,
    const __nv_bfloat16* __restrict__ Bhi, const __nv_bfloat16* __restrict__ Blo, int ldb,
    int K, float alpha, int epi,
    float* __restrict__ C, int ldc,
    __nv_bfloat16* __restrict__ O1h, __nv_bfloat16* __restrict__ O1l, int ldo,
    __half* __restrict__ H1, __half* __restrict__ H2,
    const float* __restrict__ b1, const float* __restrict__ b2)
{
    constexpr int WN   = BN / 2;
    constexpr int NJ   = WN / 8;
    constexpr int NH32 = WN / 32;
    constexpr int ABF  = 128 * RS;
    constexpr int A32B = AF32 ? 128 * RS32 : 0;
    constexpr int BB   = BN * RS;
    constexpr int OFF_AHI = A32B;
    constexpr int OFF_ALO = A32B + ABF;
    constexpr int OFF_BHI = A32B + 2 * ABF;
    constexpr int OFF_BLO = A32B + 2 * ABF + BB;
    constexpr int STAGE   = A32B + 2 * ABF + 2 * BB;

    extern __shared__ char smem[];
    uint32_t sb = smem_u32(smem);

    int tid  = threadIdx.x;
    int lane = tid & 31;
    int w    = tid >> 5;
    int wm   = w >> 1;
    int wn   = w & 1;
    int m0   = blockIdx.y * 128;
    int n0   = blockIdx.x * BN;

    float acc[2][NJ][4];
#pragma unroll
    for (int mi = 0; mi < 2; mi++)
#pragma unroll
        for (int nj = 0; nj < NJ; nj++)
#pragma unroll
            for (int q = 0; q < 4; q++) acc[mi][nj][q] = 0.0f;

    const int nc = K >> 5;

    auto load_stage = [&](int st, int k0) {
        uint32_t s0 = sb + st * STAGE;
        if (AF32) {
#pragma unroll
            for (int i = 0; i < 4; i++) {
                int idx = tid + i * 256;
                int r = idx >> 3, vv = idx & 7;
                cp16(s0 + r * RS32 + vv * 16, A32 + (long)(m0 + r) * lda + k0 + vv * 4);
            }
        } else {
#pragma unroll
            for (int i = 0; i < 2; i++) {
                int idx = tid + i * 256;
                int r = idx >> 2, vv = idx & 3;
                uint32_t so = (uint32_t)(r * RS + vv * 16);
                cp16(s0 + OFF_AHI + so, Ahi + (long)(m0 + r) * lda + k0 + vv * 8);
                cp16(s0 + OFF_ALO + so, Alo + (long)(m0 + r) * lda + k0 + vv * 8);
            }
        }
#pragma unroll
        for (int i = 0; i < BN / 64; i++) {
            int idx = tid + i * 256;
            int r = idx >> 2, vv = idx & 3;
            uint32_t so = (uint32_t)(r * RS + vv * 16);
            cp16(s0 + OFF_BHI + so, Bhi + (long)(n0 + r) * ldb + k0 + vv * 8);
            cp16(s0 + OFF_BLO + so, Blo + (long)(n0 + r) * ldb + k0 + vv * 8);
        }
        cp_commit();
    };

    auto convert_stage = [&](int st) {
        char* s0 = smem + st * STAGE;
        int r = tid >> 1, hf = tid & 1;
        float4 f[4];
#pragma unroll
        for (int q = 0; q < 4; q++)
            f[q] = *(const float4*)(s0 + r * RS32 + hf * 64 + q * 16);
        BF8 h0, h1, l0, l1;
#pragma unroll
        for (int q = 0; q < 2; q++) {
            split2(f[q].x, h0.v[q*4+0], l0.v[q*4+0]); split2(f[q].y, h0.v[q*4+1], l0.v[q*4+1]);
            split2(f[q].z, h0.v[q*4+2], l0.v[q*4+2]); split2(f[q].w, h0.v[q*4+3], l0.v[q*4+3]);
        }
#pragma unroll
        for (int q = 2; q < 4; q++) {
            split2(f[q].x, h1.v[(q-2)*4+0], l1.v[(q-2)*4+0]); split2(f[q].y, h1.v[(q-2)*4+1], l1.v[(q-2)*4+1]);
            split2(f[q].z, h1.v[(q-2)*4+2], l1.v[(q-2)*4+2]); split2(f[q].w, h1.v[(q-2)*4+3], l1.v[(q-2)*4+3]);
        }
        char* dh = s0 + OFF_AHI + r * RS + hf * 32;
        char* dl = s0 + OFF_ALO + r * RS + hf * 32;
        *(BF8*)(dh)      = h0; *(BF8*)(dh + 16) = h1;
        *(BF8*)(dl)      = l0; *(BF8*)(dl + 16) = l1;
    };

    auto compute_stage = [&](int st) {
        uint32_t aB = sb + st * STAGE + OFF_AHI;
        uint32_t bB = sb + st * STAGE + OFF_BHI;
        uint32_t l15 = (uint32_t)(lane & 15);
        uint32_t lh  = (uint32_t)(lane >> 4);
#pragma unroll
        for (int ks = 0; ks < 2; ks++) {
            uint32_t a_hi[2][4], a_lo[2][4];
#pragma unroll
            for (int mi = 0; mi < 2; mi++) {
                uint32_t ad = aB + (wm * 32 + mi * 16 + l15) * RS + ks * 32 + lh * 16;
                ldmx4(a_hi[mi], ad);
                ldmx4(a_lo[mi], ad + ABF);
            }
#pragma unroll
            for (int nh = 0; nh < NH32; nh++) {
                uint32_t b_hi[2][4], b_lo[2][4];
#pragma unroll
                for (int nt = 0; nt < 2; nt++) {
                    uint32_t bd = bB + (wn * WN + nh * 32 + nt * 16 + l15) * RS + ks * 32 + lh * 16;
                    ldmx4(b_hi[nt], bd);
                    ldmx4(b_lo[nt], bd + BB);
                }
#pragma unroll
                for (int mi = 0; mi < 2; mi++)
#pragma unroll
                    for (int nt = 0; nt < 2; nt++)
#pragma unroll
                        for (int s = 0; s < 2; s++) {
                            int nj = nh * 4 + nt * 2 + s;
                            mma_bf16(acc[mi][nj], a_hi[mi], b_hi[nt][s], b_hi[nt][s + 2]);
                            mma_bf16(acc[mi][nj], a_hi[mi], b_lo[nt][s], b_lo[nt][s + 2]);
                            mma_bf16(acc[mi][nj], a_lo[mi], b_hi[nt][s], b_hi[nt][s + 2]);
                        }
            }
        }
    };

    load_stage(0, 0);
    for (int c = 0; c < nc; c++) {
        if (c + 1 < nc) {
            load_stage((c + 1) & 1, (c + 1) << 5);
            cp_wait<1>();
        } else {
            cp_wait<0>();
        }
        __syncthreads();
        if (AF32) { convert_stage(c & 1); __syncthreads(); }
        compute_stage(c & 1);
        __syncthreads();
    }

    int rb = m0 + wm * 32 + (lane >> 2);
    int cb = n0 + wn * WN + (lane & 3) * 2;
#pragma unroll
    for (int mi = 0; mi < 2; mi++)
#pragma unroll
        for (int nj = 0; nj < NJ; nj++) {
#pragma unroll
            for (int q = 0; q < 4; q++) {
                int m = rb + mi * 16 + (q >> 1) * 8;
                int n = cb + nj * 8 + (q & 1);
                float x = acc[mi][nj][q] * alpha;
                if (epi == EPI_GELU) {
                    C[(long)m * ldc + n] =
                        0.5f * x * (1.0f + erff(x * 0.70710678118654752440f));
                } else if (epi == EPI_SPLIT) {
                    __nv_bfloat16 h, l; split2(x, h, l);
                    long o = (long)m * ldo + n;
                    O1h[o] = h; O1l[o] = l;
                } else if (epi == EPI_SPLITT) {
                    __nv_bfloat16 h, l; split2(x, h, l);
                    long o = (long)n * ldo + m;
                    O1h[o] = h; O1l[o] = l;
                } else if (epi == EPI_HALF) {
                    H1[(long)m * ldo + n] = __float2half(x);
                } else {  // EPI_DUAL16
                    long o = (long)m * ldo + n;
                    H1[o] = __float2half(x + b1[n]);
                    H2[o] = __float2half(x + b2[n]);
                }
            }
        }
}

// ---------------- GEMM wrapper kernels ---------------------------------------
__global__ __launch_bounds__(256) void proj_all(const float* __restrict__ up,
                                                const float* __restrict__ vp) {
    int z = blockIdx.z;
    if (z == 0)
        gemm_core<128, false>(g_xq_hi, g_xq_lo, nullptr, DM, g_wq_hi, g_wq_lo, DM,
            DM, 1.0f, EPI_DUAL16, nullptr, 0, nullptr, nullptr, DM,
            g_qu16, g_qv16, up, vp);
    else if (z == 1)
        gemm_core<128, false>(g_xk_hi, g_xk_lo, nullptr, DM, g_wke_hi, g_wke_lo, DM,
            DM, 1.0f, EPI_HALF, nullptr, 0, nullptr, nullptr, DM,
            g_k16, nullptr, nullptr, nullptr);
    else if (z == 2)
        gemm_core<128, false>(g_xv_hi, g_xv_lo, nullptr, DM, g_wv_hi, g_wv_lo, DM,
            DM, 1.0f, EPI_SPLITT, nullptr, 0, g_vT_hi, g_vT_lo, SEQ,
            nullptr, nullptr, nullptr, nullptr);
    else
        gemm_core<128, false>(g_re_hi, g_re_lo, nullptr, DM, g_wkr_hi, g_wkr_lo, DM,
            DM, 1.0f, EPI_HALF, nullptr, 0, nullptr, nullptr, DM,
            g_qr16, nullptr, nullptr, nullptr);
}

// ---------------- dedicated fp16 score kernel (K=64, single pass) ------------
#define SRS 144   // 64 fp16 = 128B data + 16B pad

__global__ __launch_bounds__(256) void score_kernel() {
    __shared__ __align__(16) char smem[2 * 128 * SRS];
    uint32_t sb  = smem_u32(smem);
    uint32_t sbB = sb + 128 * SRS;

    int tid = threadIdx.x, lane = tid & 31, w = tid >> 5;
    int wm = w >> 1, wn = w & 1;
    int m0 = blockIdx.y * 128, n0 = blockIdx.x * 128;
    int z = blockIdx.z, h = z & (NH - 1), mode = z >> 4;

    const __half* Ag = (mode ? g_qv16 : g_qu16) + h * DH;
    const __half* Bg = (mode ? g_qr16 : g_k16)  + h * DH;

#pragma unroll
    for (int i = 0; i < 4; i++) {
        int idx = tid + i * 256;
        int r = idx >> 3, v = idx & 7;
        cp16(sb  + r * SRS + v * 16, Ag + (long)(m0 + r) * DM + v * 8);
        cp16(sbB + r * SRS + v * 16, Bg + (long)(n0 + r) * DM + v * 8);
    }
    cp_commit(); cp_wait<0>();
    __syncthreads();

    uint32_t l15 = (uint32_t)(lane & 15);
    uint32_t lh  = (uint32_t)(lane >> 4);

    uint32_t a[2][4][4];
#pragma unroll
    for (int mi = 0; mi < 2; mi++)
#pragma unroll
        for (int ks = 0; ks < 4; ks++)
            ldmx4(a[mi][ks], sb + (wm * 32 + mi * 16 + l15) * SRS + ks * 32 + lh * 16);

    float acc[2][8][4];
#pragma unroll
    for (int mi = 0; mi < 2; mi++)
#pragma unroll
        for (int nj = 0; nj < 8; nj++)
#pragma unroll
            for (int q = 0; q < 4; q++) acc[mi][nj][q] = 0.0f;

#pragma unroll
    for (int ks = 0; ks < 4; ks++) {
#pragma unroll
        for (int nh = 0; nh < 2; nh++) {
            uint32_t b[2][4];
#pragma unroll
            for (int nt = 0; nt < 2; nt++)
                ldmx4(b[nt], sbB + (wn * 64 + nh * 32 + nt * 16 + l15) * SRS + ks * 32 + lh * 16);
#pragma unroll
            for (int mi = 0; mi < 2; mi++)
#pragma unroll
                for (int nt = 0; nt < 2; nt++)
#pragma unroll
                    for (int s = 0; s < 2; s++)
                        mma_f16(acc[mi][nh * 4 + nt * 2 + s], a[mi][ks], b[nt][s], b[nt][s + 2]);
        }
    }

    const float al = 1.0f / 32.0f;     // 1/sqrt(D_MODEL)
    int rb = m0 + wm * 32 + (lane >> 2);
    int cb = n0 + wn * 64 + (lane & 3) * 2;

    if (mode == 0) {
        __half* ac = g_ac + (long)h * SS;
#pragma unroll
        for (int mi = 0; mi < 2; mi++)
#pragma unroll
            for (int nj = 0; nj < 8; nj++) {
                int m = rb + mi * 16;
                int n = cb + nj * 8;
                *(__half2*)(ac + (long)m * SEQ + n) =
                    __floats2half2_rn(acc[mi][nj][0] * al, acc[mi][nj][1] * al);
                *(__half2*)(ac + (long)(m + 8) * SEQ + n) =
                    __floats2half2_rn(acc[mi][nj][2] * al, acc[mi][nj][3] * al);
            }
    } else {
        __half* bds = g_bds + (long)h * SS;
#pragma unroll
        for (int mi = 0; mi < 2; mi++)
#pragma unroll
            for (int nj = 0; nj < 8; nj++)
#pragma unroll
                for (int q = 0; q < 4; q++) {
                    int sp = rb + mi * 16 + (q >> 1) * 8;
                    int jp = cb + nj * 8 + (q & 1);
                    int s, j; bool ok = true;
                    if (jp >= SEQ - 1 - sp)      { s = sp;     j = jp - (SEQ - 1) + sp; }
                    else if (sp >= 1)            { s = sp - 1; j = jp + sp + 1; }
                    else ok = false;
                    if (ok) bds[(long)s * SEQ + j] = __float2half(acc[mi][nj][q] * al);
                }
    }
}

__global__ __launch_bounds__(256) void einsum_k(const float* __restrict__ w) {
    int h = blockIdx.z;
    gemm_core<64, true>(nullptr, nullptr, w + (long)h * SS, SEQ,
        g_vT_hi + (long)h * DH * SEQ, g_vT_lo + (long)h * DH * SEQ, SEQ,
        SEQ, 1.0f, EPI_SPLIT, nullptr, 0,
        g_o1_hi + h * DH, g_o1_lo + h * DH, DM,
        nullptr, nullptr, nullptr, nullptr);
}

__global__ __launch_bounds__(256) void final_k(float* __restrict__ out) {
    gemm_core<128, false>(g_o1_hi, g_o1_lo, nullptr, DM, g_wf_hi, g_wf_lo, DM,
        DM, 1.0f, EPI_GELU, out, DM,
        nullptr, nullptr, 0, nullptr, nullptr, nullptr, nullptr);
}

// ---------------- fused shift-add + softmax ----------------------------------
__global__ __launch_bounds__(256) void softmax_kernel(float* __restrict__ w,
                                                      const float* __restrict__ mask) {
    int s = blockIdx.x, h = blockIdx.y;
    long base = ((long)h * SEQ + s) * SEQ;
    __shared__ float red[256];
    int tid = threadIdx.x;
    int j0 = tid * 8;

    uint4 acr = *(const uint4*)(g_ac + base + j0);
    uint4 bdr = *(const uint4*)(g_bds + base + j0);
    float4 mk0 = *(const float4*)(mask + (long)s * SEQ + j0);
    float4 mk1 = *(const float4*)(mask + (long)s * SEQ + j0 + 4);

    float vals[8];
    {
        const __half2* ah = (const __half2*)&acr;
        const __half2* bh = (const __half2*)&bdr;
        const float* mk = (const float*)&mk0;
#pragma unroll
        for (int i = 0; i < 4; i++) {
            float2 a2 = __half22float2(ah[i]);
            float2 b2 = __half22float2(bh[i]);
            vals[2*i]   = a2.x + b2.x;
            vals[2*i+1] = a2.y + b2.y;
        }
#pragma unroll
        for (int i = 0; i < 4; i++) vals[i] += mk[i];
        const float* mk2 = (const float*)&mk1;
#pragma unroll
        for (int i = 0; i < 4; i++) vals[4 + i] += mk2[i];
    }
    // zero position: j == s+1 (unwritten in scatter)
    int zp = s + 1 - j0;
    if (zp >= 0 && zp < 8) {
        float2 a2 = __half22float2(((const __half2*)&acr)[zp >> 1]);
        float m = ((zp & 4) ? ((const float*)&mk1)[zp & 3] : ((const float*)&mk0)[zp]);
        vals[zp] = ((zp & 1) ? a2.y : a2.x) + m;
    }

    float vmax = -3.0e38f;
#pragma unroll
    for (int i = 0; i < 8; i++) vmax = fmaxf(vmax, vals[i]);
    red[tid] = vmax; __syncthreads();
    for (int st = 128; st > 0; st >>= 1) {
        if (tid < st) red[tid] = fmaxf(red[tid], red[tid + st]);
        __syncthreads();
    }
    vmax = red[0]; __syncthreads();

    float sum = 0.0f;
#pragma unroll
    for (int i = 0; i < 8; i++) {
        vals[i] = expf(vals[i] - vmax);
        sum += vals[i];
    }
    red[tid] = sum; __syncthreads();
    for (int st = 128; st > 0; st >>= 1) {
        if (tid < st) red[tid] += red[tid + st];
        __syncthreads();
    }
    sum = red[0];
    float inv = 1.0f / sum;

    float4 o0 = make_float4(vals[0] * inv, vals[1] * inv, vals[2] * inv, vals[3] * inv);
    float4 o1 = make_float4(vals[4] * inv, vals[5] * inv, vals[6] * inv, vals[7] * inv);
    *(float4*)(w + base + j0)     = o0;
    *(float4*)(w + base + j0 + 4) = o1;

    if (tid == 0) atomicMax(&g_headmax[h], __float_as_int(inv));
}

__global__ void loss_kernel(float* __restrict__ out) {
    if (threadIdx.x == 0) {
        float s = 0.0f;
        for (int h = 0; h < NH; h++) s += __int_as_float(g_headmax[h]);
        out[(long)SEQ * DM + (long)NH * SS] = s / (float)NH;
    }
}

// ---------------- launcher ---------------------------------------------------
extern "C" void kernel_launch(void* const* d_in, const int* in_sizes, int n_in,
                              void* d_out, int out_size) {
    (void)in_sizes; (void)n_in; (void)out_size;
    const float* query = (const float*)d_in[0];
    const float* key   = (const float*)d_in[1];
    const float* value = (const float*)d_in[2];
    const float* mask  = (const float*)d_in[3];
    const float* Wq    = (const float*)d_in[4];
    const float* Wke   = (const float*)d_in[5];
    const float* Wkr   = (const float*)d_in[6];
    const float* Wv    = (const float*)d_in[7];
    const float* Wf    = (const float*)d_in[8];
    const float* up    = (const float*)d_in[9];
    const float* vp    = (const float*)d_in[10];

    float* out = (float*)d_out;
    float* w   = out + (long)SEQ * DM;

    constexpr int SMEM_BF = 2 * (2 * 128 * RS + 2 * 128 * RS);                 // 81920
    constexpr int SMEM_E  = 2 * (128 * RS32 + 2 * 128 * RS + 2 * 64 * RS);     // 98304
    cudaFuncSetAttribute(proj_all, cudaFuncAttributeMaxDynamicSharedMemorySize, SMEM_BF);
    cudaFuncSetAttribute(final_k,  cudaFuncAttributeMaxDynamicSharedMemorySize, SMEM_BF);
    cudaFuncSetAttribute(einsum_k, cudaFuncAttributeMaxDynamicSharedMemorySize, SMEM_E);

    // 1. relenc (+ headmax init) and merged input/weight splits
    relenc_kernel<<<SEQ * DM / 1024, 256>>>();
    split_all<<<dim3(SEQ * DM / 1024, 1, 8), 256>>>(query, key, value, Wq, Wke, Wkr, Wv, Wf);

    // 2. all projections, one launch
    proj_all<<<dim3(DM / 128, SEQ / 128, 4), 256, SMEM_BF>>>(up, vp);

    // 3. scores: fp16 single-pass (z<16: A_C -> g_ac; z>=16: B_D shifted -> g_bds)
    score_kernel<<<dim3(SEQ / 128, SEQ / 128, 2 * NH), 256>>>();

    // 4. fused shift-add + mask + softmax (+ per-head max weight)
    softmax_kernel<<<dim3(SEQ, NH), 256>>>(w, mask);

    // 5. einsum with in-kernel fp32->bf16 split of weights
    einsum_k<<<dim3(1, SEQ / 128, NH), 256, SMEM_E>>>(w);

    // 6. final projection + exact GELU
    final_k<<<dim3(DM / 128, SEQ / 128, 1), 256, SMEM_BF>>>(out);

    // 7. loss scalar
    loss_kernel<<<1, 1>>>(out);
}

// round 8
// speedup vs baseline: 3.6589x; 1.3182x over previous
#include <cuda_runtime.h>
#include <cuda_bf16.h>
#include <cuda_fp16.h>
#include <math.h>
#include <stdint.h>

#define SEQ 2048
#define DM  1024
#define NH  16
#define DH  64
#define SS  ((long)SEQ * SEQ)

// ---------------- scratch (device globals; no allocations allowed) ----------
__device__ __half g_bds[(size_t)NH * SEQ * SEQ];            // B_D_hat (unshifted), fp16
__device__ __half g_ac[(size_t)NH * SEQ * SEQ];             // A_C scores, fp16
__device__ __half g_w16[(size_t)NH * SEQ * SEQ];            // softmax weights, fp16

__device__ __nv_bfloat16 g_xq_hi[SEQ * DM], g_xq_lo[SEQ * DM];
__device__ __nv_bfloat16 g_xk_hi[SEQ * DM], g_xk_lo[SEQ * DM];
__device__ __nv_bfloat16 g_xv_hi[SEQ * DM], g_xv_lo[SEQ * DM];
__device__ __nv_bfloat16 g_re_hi[SEQ * DM], g_re_lo[SEQ * DM];

__device__ __nv_bfloat16 g_wq_hi[DM * DM],  g_wq_lo[DM * DM];
__device__ __nv_bfloat16 g_wke_hi[DM * DM], g_wke_lo[DM * DM];
__device__ __nv_bfloat16 g_wkr_hi[DM * DM], g_wkr_lo[DM * DM];
__device__ __nv_bfloat16 g_wv_hi[DM * DM],  g_wv_lo[DM * DM];
__device__ __nv_bfloat16 g_wf_hi[DM * DM],  g_wf_lo[DM * DM];

__device__ __half g_qu16[SEQ * DM], g_qv16[SEQ * DM];       // fp16 score operands
__device__ __half g_k16[SEQ * DM],  g_qr16[SEQ * DM];

__device__ __half g_v16T[DM * SEQ];                          // [h*64+d][f], fp16
__device__ __nv_bfloat16 g_o1_hi[SEQ * DM], g_o1_lo[SEQ * DM];

__device__ int g_headmax[NH];

// ---------------- helpers ----------------------------------------------------
__device__ __forceinline__ uint32_t smem_u32(const void* p) {
    uint32_t a;
    asm("{ .reg .u64 t; cvta.to.shared.u64 t, %1; cvt.u32.u64 %0, t; }" : "=r"(a) : "l"(p));
    return a;
}
__device__ __forceinline__ void cp16(uint32_t s, const void* g) {
    asm volatile("cp.async.cg.shared.global [%0], [%1], 16;" :: "r"(s), "l"(g));
}
__device__ __forceinline__ void cp_commit() {
    asm volatile("cp.async.commit_group;" ::: "memory");
}
template <int N>
__device__ __forceinline__ void cp_wait() {
    asm volatile("cp.async.wait_group %0;" :: "n"(N) : "memory");
}
__device__ __forceinline__ void ldmx4(uint32_t* r, uint32_t addr) {
    asm volatile("ldmatrix.sync.aligned.m8n8.x4.shared.b16 {%0,%1,%2,%3}, [%4];"
                 : "=r"(r[0]), "=r"(r[1]), "=r"(r[2]), "=r"(r[3]) : "r"(addr));
}
__device__ __forceinline__ void mma_bf16(float* c, const uint32_t* a, uint32_t b0, uint32_t b1) {
    asm volatile("mma.sync.aligned.m16n8k16.row.col.f32.bf16.bf16.f32 "
                 "{%0,%1,%2,%3}, {%4,%5,%6,%7}, {%8,%9}, {%0,%1,%2,%3};"
                 : "+f"(c[0]), "+f"(c[1]), "+f"(c[2]), "+f"(c[3])
                 : "r"(a[0]), "r"(a[1]), "r"(a[2]), "r"(a[3]), "r"(b0), "r"(b1));
}
__device__ __forceinline__ void mma_f16(float* c, const uint32_t* a, uint32_t b0, uint32_t b1) {
    asm volatile("mma.sync.aligned.m16n8k16.row.col.f32.f16.f16.f32 "
                 "{%0,%1,%2,%3}, {%4,%5,%6,%7}, {%8,%9}, {%0,%1,%2,%3};"
                 : "+f"(c[0]), "+f"(c[1]), "+f"(c[2]), "+f"(c[3])
                 : "r"(a[0]), "r"(a[1]), "r"(a[2]), "r"(a[3]), "r"(b0), "r"(b1));
}
__device__ __forceinline__ void split2(float x, __nv_bfloat16& h, __nv_bfloat16& l) {
    h = __float2bfloat16(x);
    l = __float2bfloat16(x - __bfloat162float(h));
}

struct alignas(8)  BF4 { __nv_bfloat16 v[4]; };

// ---------------- merged elementwise split -----------------------------------
__global__ __launch_bounds__(256) void split_all(
    const float* __restrict__ q, const float* __restrict__ k, const float* __restrict__ v,
    const float* __restrict__ wq, const float* __restrict__ wke, const float* __restrict__ wkr,
    const float* __restrict__ wv, const float* __restrict__ wf)
{
    int z = blockIdx.z;
    long n = (z < 3) ? (long)SEQ * DM : (long)DM * DM;
    long i = ((long)blockIdx.x * 256 + threadIdx.x) * 4;
    if (i >= n) return;
    const float* src; __nv_bfloat16 *dh, *dl;
    switch (z) {
        case 0: src = q;   dh = g_xq_hi; dl = g_xq_lo; break;
        case 1: src = k;   dh = g_xk_hi; dl = g_xk_lo; break;
        case 2: src = v;   dh = g_xv_hi; dl = g_xv_lo; break;
        case 3: src = wq;  dh = g_wq_hi;  dl = g_wq_lo;  break;
        case 4: src = wke; dh = g_wke_hi; dl = g_wke_lo; break;
        case 5: src = wkr; dh = g_wkr_hi; dl = g_wkr_lo; break;
        case 6: src = wv;  dh = g_wv_hi;  dl = g_wv_lo;  break;
        default: src = wf; dh = g_wf_hi;  dl = g_wf_lo;  break;
    }
    float4 x = *(const float4*)(src + i);
    BF4 h, l;
    split2(x.x, h.v[0], l.v[0]); split2(x.y, h.v[1], l.v[1]);
    split2(x.z, h.v[2], l.v[2]); split2(x.w, h.v[3], l.v[3]);
    *(BF4*)(dh + i) = h;
    *(BF4*)(dl + i) = l;
}

// ---------------- relative positional encoding (fp32, split output) ----------
__global__ __launch_bounds__(256) void relenc_kernel() {
    if (blockIdx.x == 0 && threadIdx.x < NH) g_headmax[threadIdx.x] = 0;
    long i = ((long)blockIdx.x * 256 + threadIdx.x) * 4;
    if (i >= (long)SEQ * DM) return;
    int f = (int)(i / DM), c0 = (int)(i % DM);
    float p = (float)(SEQ - 1 - f);
    BF4 h, l;
#pragma unroll
    for (int t = 0; t < 4; t++) {
        int c = c0 + t;
        float e  = (float)(c & ~1) * (1.0f / (float)DM);
        float dv = exp2f(-e * 13.287712379549449f);    // log2(10000)
        float ang = p * dv;
        float s, cs; sincosf(ang, &s, &cs);
        split2((c & 1) ? cs : s, h.v[t], l.v[t]);
    }
    *(BF4*)(g_re_hi + i) = h;
    *(BF4*)(g_re_lo + i) = l;
}

// ---------------- split-bf16 HMMA GEMM core (projections / final) ------------
#define EPI_GELU   1
#define EPI_SPLIT  2
#define EPI_HALF   6
#define EPI_DUAL16 7
#define EPI_HALFT  8

#define RS 80            // bf16 smem row stride in bytes (40 bf16)

template <int BN>
__device__ __forceinline__ void gemm_core(
    const __nv_bfloat16* __restrict__ Ahi, const __nv_bfloat16* __restrict__ Alo, int lda,
    const __nv_bfloat16* __restrict__ Bhi, const __nv_bfloat16* __restrict__ Blo, int ldb,
    int K, float alpha, int epi,
    float* __restrict__ C, int ldc,
    __nv_bfloat16* __restrict__ O1h, __nv_bfloat16* __restrict__ O1l, int ldo,
    __half* __restrict__ H1, __half* __restrict__ H2,
    const float* __restrict__ b1, const float* __restrict__ b2)
{
    constexpr int WN   = BN / 2;
    constexpr int NJ   = WN / 8;
    constexpr int NH32 = WN / 32;
    constexpr int ABF  = 128 * RS;
    constexpr int BB   = BN * RS;
    constexpr int OFF_BHI = 2 * ABF;
    constexpr int STAGE   = 2 * ABF + 2 * BB;

    extern __shared__ char smem[];
    uint32_t sb = smem_u32(smem);

    int tid  = threadIdx.x;
    int lane = tid & 31;
    int w    = tid >> 5;
    int wm   = w >> 1;
    int wn   = w & 1;
    int m0   = blockIdx.y * 128;
    int n0   = blockIdx.x * BN;

    float acc[2][NJ][4];
#pragma unroll
    for (int mi = 0; mi < 2; mi++)
#pragma unroll
        for (int nj = 0; nj < NJ; nj++)
#pragma unroll
            for (int q = 0; q < 4; q++) acc[mi][nj][q] = 0.0f;

    const int nc = K >> 5;

    auto load_stage = [&](int st, int k0) {
        uint32_t s0 = sb + st * STAGE;
#pragma unroll
        for (int i = 0; i < 2; i++) {
            int idx = tid + i * 256;
            int r = idx >> 2, vv = idx & 3;
            uint32_t so = (uint32_t)(r * RS + vv * 16);
            cp16(s0 + so,       Ahi + (long)(m0 + r) * lda + k0 + vv * 8);
            cp16(s0 + ABF + so, Alo + (long)(m0 + r) * lda + k0 + vv * 8);
        }
#pragma unroll
        for (int i = 0; i < BN / 64; i++) {
            int idx = tid + i * 256;
            int r = idx >> 2, vv = idx & 3;
            uint32_t so = (uint32_t)(r * RS + vv * 16);
            cp16(s0 + OFF_BHI + so,      Bhi + (long)(n0 + r) * ldb + k0 + vv * 8);
            cp16(s0 + OFF_BHI + BB + so, Blo + (long)(n0 + r) * ldb + k0 + vv * 8);
        }
        cp_commit();
    };

    auto compute_stage = [&](int st) {
        uint32_t aB = sb + st * STAGE;
        uint32_t bB = sb + st * STAGE + OFF_BHI;
        uint32_t l15 = (uint32_t)(lane & 15);
        uint32_t lh  = (uint32_t)(lane >> 4);
#pragma unroll
        for (int ks = 0; ks < 2; ks++) {
            uint32_t a_hi[2][4], a_lo[2][4];
#pragma unroll
            for (int mi = 0; mi < 2; mi++) {
                uint32_t ad = aB + (wm * 32 + mi * 16 + l15) * RS + ks * 32 + lh * 16;
                ldmx4(a_hi[mi], ad);
                ldmx4(a_lo[mi], ad + ABF);
            }
#pragma unroll
            for (int nh = 0; nh < NH32; nh++) {
                uint32_t b_hi[2][4], b_lo[2][4];
#pragma unroll
                for (int nt = 0; nt < 2; nt++) {
                    uint32_t bd = bB + (wn * WN + nh * 32 + nt * 16 + l15) * RS + ks * 32 + lh * 16;
                    ldmx4(b_hi[nt], bd);
                    ldmx4(b_lo[nt], bd + BB);
                }
#pragma unroll
                for (int mi = 0; mi < 2; mi++)
#pragma unroll
                    for (int nt = 0; nt < 2; nt++)
#pragma unroll
                        for (int s = 0; s < 2; s++) {
                            int nj = nh * 4 + nt * 2 + s;
                            mma_bf16(acc[mi][nj], a_hi[mi], b_hi[nt][s], b_hi[nt][s + 2]);
                            mma_bf16(acc[mi][nj], a_hi[mi], b_lo[nt][s], b_lo[nt][s + 2]);
                            mma_bf16(acc[mi][nj], a_lo[mi], b_hi[nt][s], b_hi[nt][s + 2]);
                        }
            }
        }
    };

    load_stage(0, 0);
    for (int c = 0; c < nc; c++) {
        if (c + 1 < nc) {
            load_stage((c + 1) & 1, (c + 1) << 5);
            cp_wait<1>();
        } else {
            cp_wait<0>();
        }
        __syncthreads();
        compute_stage(c & 1);
        __syncthreads();
    }

    int rb = m0 + wm * 32 + (lane >> 2);
    int cb = n0 + wn * WN + (lane & 3) * 2;
#pragma unroll
    for (int mi = 0; mi < 2; mi++)
#pragma unroll
        for (int nj = 0; nj < NJ; nj++) {
#pragma unroll
            for (int q = 0; q < 4; q++) {
                int m = rb + mi * 16 + (q >> 1) * 8;
                int n = cb + nj * 8 + (q & 1);
                float x = acc[mi][nj][q] * alpha;
                if (epi == EPI_GELU) {
                    C[(long)m * ldc + n] =
                        0.5f * x * (1.0f + erff(x * 0.70710678118654752440f));
                } else if (epi == EPI_SPLIT) {
                    __nv_bfloat16 h, l; split2(x, h, l);
                    long o = (long)m * ldo + n;
                    O1h[o] = h; O1l[o] = l;
                } else if (epi == EPI_HALF) {
                    H1[(long)m * ldo + n] = __float2half(x);
                } else if (epi == EPI_HALFT) {
                    H1[(long)n * ldo + m] = __float2half(x);
                } else {  // EPI_DUAL16
                    long o = (long)m * ldo + n;
                    H1[o] = __float2half(x + b1[n]);
                    H2[o] = __float2half(x + b2[n]);
                }
            }
        }
}

// ---------------- GEMM wrapper kernels ---------------------------------------
__global__ __launch_bounds__(256) void proj_all(const float* __restrict__ up,
                                                const float* __restrict__ vp) {
    int z = blockIdx.z;
    if (z == 0)
        gemm_core<128>(g_xq_hi, g_xq_lo, DM, g_wq_hi, g_wq_lo, DM,
            DM, 1.0f, EPI_DUAL16, nullptr, 0, nullptr, nullptr, DM,
            g_qu16, g_qv16, up, vp);
    else if (z == 1)
        gemm_core<128>(g_xk_hi, g_xk_lo, DM, g_wke_hi, g_wke_lo, DM,
            DM, 1.0f, EPI_HALF, nullptr, 0, nullptr, nullptr, DM,
            g_k16, nullptr, nullptr, nullptr);
    else if (z == 2)
        gemm_core<128>(g_xv_hi, g_xv_lo, DM, g_wv_hi, g_wv_lo, DM,
            DM, 1.0f, EPI_HALFT, nullptr, 0, nullptr, nullptr, SEQ,
            g_v16T, nullptr, nullptr, nullptr);
    else
        gemm_core<128>(g_re_hi, g_re_lo, DM, g_wkr_hi, g_wkr_lo, DM,
            DM, 1.0f, EPI_HALF, nullptr, 0, nullptr, nullptr, DM,
            g_qr16, nullptr, nullptr, nullptr);
}

// ---------------- dedicated fp16 score kernel (K=64, single pass) ------------
#define SRS 144   // 64 fp16 = 128B data + 16B pad

__global__ __launch_bounds__(256) void score_kernel() {
    __shared__ __align__(16) char smem[2 * 128 * SRS];
    uint32_t sb  = smem_u32(smem);
    uint32_t sbB = sb + 128 * SRS;

    int tid = threadIdx.x, lane = tid & 31, w = tid >> 5;
    int wm = w >> 1, wn = w & 1;
    int m0 = blockIdx.y * 128, n0 = blockIdx.x * 128;
    int z = blockIdx.z, h = z & (NH - 1), mode = z >> 4;

    const __half* Ag = (mode ? g_qv16 : g_qu16) + h * DH;
    const __half* Bg = (mode ? g_qr16 : g_k16)  + h * DH;

#pragma unroll
    for (int i = 0; i < 4; i++) {
        int idx = tid + i * 256;
        int r = idx >> 3, v = idx & 7;
        cp16(sb  + r * SRS + v * 16, Ag + (long)(m0 + r) * DM + v * 8);
        cp16(sbB + r * SRS + v * 16, Bg + (long)(n0 + r) * DM + v * 8);
    }
    cp_commit(); cp_wait<0>();
    __syncthreads();

    uint32_t l15 = (uint32_t)(lane & 15);
    uint32_t lh  = (uint32_t)(lane >> 4);

    uint32_t a[2][4][4];
#pragma unroll
    for (int mi = 0; mi < 2; mi++)
#pragma unroll
        for (int ks = 0; ks < 4; ks++)
            ldmx4(a[mi][ks], sb + (wm * 32 + mi * 16 + l15) * SRS + ks * 32 + lh * 16);

    float acc[2][8][4];
#pragma unroll
    for (int mi = 0; mi < 2; mi++)
#pragma unroll
        for (int nj = 0; nj < 8; nj++)
#pragma unroll
            for (int q = 0; q < 4; q++) acc[mi][nj][q] = 0.0f;

#pragma unroll
    for (int ks = 0; ks < 4; ks++) {
#pragma unroll
        for (int nh = 0; nh < 2; nh++) {
            uint32_t b[2][4];
#pragma unroll
            for (int nt = 0; nt < 2; nt++)
                ldmx4(b[nt], sbB + (wn * 64 + nh * 32 + nt * 16 + l15) * SRS + ks * 32 + lh * 16);
#pragma unroll
            for (int mi = 0; mi < 2; mi++)
#pragma unroll
                for (int nt = 0; nt < 2; nt++)
#pragma unroll
                    for (int s = 0; s < 2; s++)
                        mma_f16(acc[mi][nh * 4 + nt * 2 + s], a[mi][ks], b[nt][s], b[nt][s + 2]);
        }
    }

    const float al = 1.0f / 32.0f;     // 1/sqrt(D_MODEL)
    int rb = m0 + wm * 32 + (lane >> 2);
    int cb = n0 + wn * 64 + (lane & 3) * 2;

    __half* dst = (mode ? g_bds : g_ac) + (long)h * SS;
#pragma unroll
    for (int mi = 0; mi < 2; mi++)
#pragma unroll
        for (int nj = 0; nj < 8; nj++) {
            int m = rb + mi * 16;
            int n = cb + nj * 8;
            *(__half2*)(dst + (long)m * SEQ + n) =
                __floats2half2_rn(acc[mi][nj][0] * al, acc[mi][nj][1] * al);
            *(__half2*)(dst + (long)(m + 8) * SEQ + n) =
                __floats2half2_rn(acc[mi][nj][2] * al, acc[mi][nj][3] * al);
        }
}

// ---------------- fp16 einsum: out1 = w16 @ v16T^T ---------------------------
#define ESTAGE (128 * SRS + 64 * SRS)

__global__ __launch_bounds__(256) void einsum16_k() {
    extern __shared__ char smem[];
    uint32_t sb = smem_u32(smem);

    int tid = threadIdx.x, lane = tid & 31, w = tid >> 5;
    int wm = w >> 1, wn = w & 1;
    int m0 = blockIdx.y * 128;
    int h  = blockIdx.z;

    const __half* A = g_w16  + (long)h * SS;        // 2048 x 2048
    const __half* B = g_v16T + (long)h * DH * SEQ;  // 64 x 2048

    float acc[2][4][4];
#pragma unroll
    for (int mi = 0; mi < 2; mi++)
#pragma unroll
        for (int nj = 0; nj < 4; nj++)
#pragma unroll
            for (int q = 0; q < 4; q++) acc[mi][nj][q] = 0.0f;

    auto load_stage = [&](int st, int k0) {
        uint32_t s0 = sb + st * ESTAGE;
#pragma unroll
        for (int i = 0; i < 4; i++) {
            int idx = tid + i * 256;
            int r = idx >> 3, v = idx & 7;
            cp16(s0 + r * SRS + v * 16, A + (long)(m0 + r) * SEQ + k0 + v * 8);
        }
#pragma unroll
        for (int i = 0; i < 2; i++) {
            int idx = tid + i * 256;
            int r = idx >> 3, v = idx & 7;
            cp16(s0 + 128 * SRS + r * SRS + v * 16, B + (long)r * SEQ + k0 + v * 8);
        }
        cp_commit();
    };

    auto compute_stage = [&](int st) {
        uint32_t aB = sb + st * ESTAGE;
        uint32_t bB = aB + 128 * SRS;
        uint32_t l15 = (uint32_t)(lane & 15);
        uint32_t lh  = (uint32_t)(lane >> 4);
#pragma unroll
        for (int ks = 0; ks < 4; ks++) {
            uint32_t a[2][4];
#pragma unroll
            for (int mi = 0; mi < 2; mi++)
                ldmx4(a[mi], aB + (wm * 32 + mi * 16 + l15) * SRS + ks * 32 + lh * 16);
            uint32_t b[2][4];
#pragma unroll
            for (int nt = 0; nt < 2; nt++)
                ldmx4(b[nt], bB + (wn * 32 + nt * 16 + l15) * SRS + ks * 32 + lh * 16);
#pragma unroll
            for (int mi = 0; mi < 2; mi++)
#pragma unroll
                for (int nt = 0; nt < 2; nt++)
#pragma unroll
                    for (int s = 0; s < 2; s++)
                        mma_f16(acc[mi][nt * 2 + s], a[mi], b[nt][s], b[nt][s + 2]);
        }
    };

    load_stage(0, 0);
    const int nc = SEQ / 64;
    for (int c = 0; c < nc; c++) {
        if (c + 1 < nc) {
            load_stage((c + 1) & 1, (c + 1) * 64);
            cp_wait<1>();
        } else {
            cp_wait<0>();
        }
        __syncthreads();
        compute_stage(c & 1);
        __syncthreads();
    }

    int rb = m0 + wm * 32 + (lane >> 2);
    int cb = h * DH + wn * 32 + (lane & 3) * 2;
#pragma unroll
    for (int mi = 0; mi < 2; mi++)
#pragma unroll
        for (int nj = 0; nj < 4; nj++)
#pragma unroll
            for (int q = 0; q < 4; q++) {
                int m = rb + mi * 16 + (q >> 1) * 8;
                int n = cb + nj * 8 + (q & 1);
                __nv_bfloat16 hh, ll; split2(acc[mi][nj][q], hh, ll);
                long o = (long)m * DM + n;
                g_o1_hi[o] = hh; g_o1_lo[o] = ll;
            }
}

__global__ __launch_bounds__(256) void final_k(float* __restrict__ out) {
    gemm_core<128>(g_o1_hi, g_o1_lo, DM, g_wf_hi, g_wf_lo, DM,
        DM, 1.0f, EPI_GELU, out, DM,
        nullptr, nullptr, 0, nullptr, nullptr, nullptr, nullptr);
}

// ---------------- fused gather-shift + mask + softmax ------------------------
__global__ __launch_bounds__(256) void softmax_kernel(float* __restrict__ w,
                                                      const float* __restrict__ mask) {
    int s = blockIdx.x, h = blockIdx.y;
    long base = ((long)h * SEQ + s) * SEQ;
    const __half* hat = g_bds + (long)h * SS;
    __shared__ float red[256];
    int tid = threadIdx.x;
    int j0 = tid * 8;

    // rel-shift gather geometry (two contiguous runs per row)
    long flat0 = (long)s * SEQ + (SEQ - 1);
    int sp0 = (int)(flat0 / (SEQ + 1));
    int jp0 = (int)(flat0 - (long)sp0 * (SEQ + 1));
    int jwrap = (SEQ + 1) - jp0;
    long base1 = (long)sp0 * SEQ + jp0;
    long base2 = (long)(sp0 + 1) * SEQ - jwrap;

    uint4 acr = *(const uint4*)(g_ac + base + j0);
    float4 mk0 = *(const float4*)(mask + (long)s * SEQ + j0);
    float4 mk1 = *(const float4*)(mask + (long)s * SEQ + j0 + 4);

    float vals[8];
    {
        const __half2* ah = (const __half2*)&acr;
#pragma unroll
        for (int i = 0; i < 4; i++) {
            float2 a2 = __half22float2(ah[i]);
            vals[2 * i]     = a2.x;
            vals[2 * i + 1] = a2.y;
        }
        const float* mka = (const float*)&mk0;
        const float* mkb = (const float*)&mk1;
#pragma unroll
        for (int i = 0; i < 4; i++) vals[i]     += mka[i];
#pragma unroll
        for (int i = 0; i < 4; i++) vals[4 + i] += mkb[i];
#pragma unroll
        for (int i = 0; i < 8; i++) {
            int j = j0 + i;
            if (j != s + 1)
                vals[i] += __half2float(hat[(j < jwrap ? base1 : base2) + j]);
        }
    }

    float vmax = -3.0e38f;
#pragma unroll
    for (int i = 0; i < 8; i++) vmax = fmaxf(vmax, vals[i]);
    red[tid] = vmax; __syncthreads();
    for (int st = 128; st > 0; st >>= 1) {
        if (tid < st) red[tid] = fmaxf(red[tid], red[tid + st]);
        __syncthreads();
    }
    vmax = red[0]; __syncthreads();

    float sum = 0.0f;
#pragma unroll
    for (int i = 0; i < 8; i++) {
        vals[i] = expf(vals[i] - vmax);
        sum += vals[i];
    }
    red[tid] = sum; __syncthreads();
    for (int st = 128; st > 0; st >>= 1) {
        if (tid < st) red[tid] += red[tid + st];
        __syncthreads();
    }
    sum = red[0];
    float inv = 1.0f / sum;

    float4 o0 = make_float4(vals[0] * inv, vals[1] * inv, vals[2] * inv, vals[3] * inv);
    float4 o1 = make_float4(vals[4] * inv, vals[5] * inv, vals[6] * inv, vals[7] * inv);
    *(float4*)(w + base + j0)     = o0;
    *(float4*)(w + base + j0 + 4) = o1;

    uint2 h16;
    __half2* hp = (__half2*)&h16;
    hp[0] = __floats2half2_rn(o0.x, o0.y);
    hp[1] = __floats2half2_rn(o0.z, o0.w);
    *(uint2*)(g_w16 + base + j0) = h16;
    hp[0] = __floats2half2_rn(o1.x, o1.y);
    hp[1] = __floats2half2_rn(o1.z, o1.w);
    *(uint2*)(g_w16 + base + j0 + 4) = h16;

    if (tid == 0) atomicMax(&g_headmax[h], __float_as_int(inv));
}

__global__ void loss_kernel(float* __restrict__ out) {
    if (threadIdx.x == 0) {
        float s = 0.0f;
        for (int h = 0; h < NH; h++) s += __int_as_float(g_headmax[h]);
        out[(long)SEQ * DM + (long)NH * SS] = s / (float)NH;
    }
}

// ---------------- launcher ---------------------------------------------------
extern "C" void kernel_launch(void* const* d_in, const int* in_sizes, int n_in,
                              void* d_out, int out_size) {
    (void)in_sizes; (void)n_in; (void)out_size;
    const float* query = (const float*)d_in[0];
    const float* key   = (const float*)d_in[1];
    const float* value = (const float*)d_in[2];
    const float* mask  = (const float*)d_in[3];
    const float* Wq    = (const float*)d_in[4];
    const float* Wke   = (const float*)d_in[5];
    const float* Wkr   = (const float*)d_in[6];
    const float* Wv    = (const float*)d_in[7];
    const float* Wf    = (const float*)d_in[8];
    const float* up    = (const float*)d_in[9];
    const float* vp    = (const float*)d_in[10];

    float* out = (float*)d_out;
    float* w   = out + (long)SEQ * DM;

    constexpr int SMEM_BF = 2 * (2 * 128 * RS + 2 * 128 * RS);   // 81920
    constexpr int SMEM_E  = 2 * ESTAGE;                          // 55296
    cudaFuncSetAttribute(proj_all,   cudaFuncAttributeMaxDynamicSharedMemorySize, SMEM_BF);
    cudaFuncSetAttribute(final_k,    cudaFuncAttributeMaxDynamicSharedMemorySize, SMEM_BF);
    cudaFuncSetAttribute(einsum16_k, cudaFuncAttributeMaxDynamicSharedMemorySize, SMEM_E);

    // 1. relenc (+ headmax init) and merged input/weight splits
    relenc_kernel<<<SEQ * DM / 1024, 256>>>();
    split_all<<<dim3(SEQ * DM / 1024, 1, 8), 256>>>(query, key, value, Wq, Wke, Wkr, Wv, Wf);

    // 2. all projections, one launch
    proj_all<<<dim3(DM / 128, SEQ / 128, 4), 256, SMEM_BF>>>(up, vp);

    // 3. scores: fp16 single-pass, coalesced stores (z<16: A_C; z>=16: B_D_hat)
    score_kernel<<<dim3(SEQ / 128, SEQ / 128, 2 * NH), 256>>>();

    // 4. fused gather-shift + mask + softmax; emits w (fp32) + w16 (fp16)
    softmax_kernel<<<dim3(SEQ, NH), 256>>>(w, mask);

    // 5. fp16 single-pass einsum -> o1 (bf16 hi/lo)
    einsum16_k<<<dim3(1, SEQ / 128, NH), 256, SMEM_E>>>();

    // 6. final projection + exact GELU
    final_k<<<dim3(DM / 128, SEQ / 128, 1), 256, SMEM_BF>>>(out);

    // 7. loss scalar
    loss_kernel<<<1, 1>>>(out);
}

// round 9
// speedup vs baseline: 3.9224x; 1.0720x over previous
#include <cuda_runtime.h>
#include <cuda_bf16.h>
#include <cuda_fp16.h>
#include <math.h>
#include <stdint.h>

#define SEQ 2048
#define DM  1024
#define NH  16
#define DH  64
#define SS  ((long)SEQ * SEQ)

// ---------------- scratch (device globals; no allocations allowed) ----------
__device__ __half g_bds[(size_t)NH * SEQ * SEQ];            // B_D_hat (unshifted), fp16
__device__ __half g_ac[(size_t)NH * SEQ * SEQ];             // A_C scores, fp16
__device__ __half g_w16[(size_t)NH * SEQ * SEQ];            // softmax weights, fp16

__device__ __nv_bfloat16 g_xq_hi[SEQ * DM], g_xq_lo[SEQ * DM];
__device__ __nv_bfloat16 g_xk_hi[SEQ * DM], g_xk_lo[SEQ * DM];
__device__ __nv_bfloat16 g_xv_hi[SEQ * DM], g_xv_lo[SEQ * DM];
__device__ __nv_bfloat16 g_re_hi[SEQ * DM], g_re_lo[SEQ * DM];

__device__ __nv_bfloat16 g_wq_hi[DM * DM],  g_wq_lo[DM * DM];
__device__ __nv_bfloat16 g_wke_hi[DM * DM], g_wke_lo[DM * DM];
__device__ __nv_bfloat16 g_wkr_hi[DM * DM], g_wkr_lo[DM * DM];
__device__ __nv_bfloat16 g_wv_hi[DM * DM],  g_wv_lo[DM * DM];
__device__ __nv_bfloat16 g_wf_hi[DM * DM],  g_wf_lo[DM * DM];

__device__ __half g_qu16[SEQ * DM], g_qv16[SEQ * DM];       // fp16 score operands
__device__ __half g_k16[SEQ * DM],  g_qr16[SEQ * DM];

__device__ __half g_v16T[DM * SEQ];                          // [h*64+d][f], fp16
__device__ __nv_bfloat16 g_o1_hi[SEQ * DM], g_o1_lo[SEQ * DM];

__device__ int g_headmax[NH];

// ---------------- helpers ----------------------------------------------------
__device__ __forceinline__ uint32_t smem_u32(const void* p) {
    uint32_t a;
    asm("{ .reg .u64 t; cvta.to.shared.u64 t, %1; cvt.u32.u64 %0, t; }" : "=r"(a) : "l"(p));
    return a;
}
__device__ __forceinline__ void cp16(uint32_t s, const void* g) {
    asm volatile("cp.async.cg.shared.global [%0], [%1], 16;" :: "r"(s), "l"(g));
}
__device__ __forceinline__ void cp_commit() {
    asm volatile("cp.async.commit_group;" ::: "memory");
}
template <int N>
__device__ __forceinline__ void cp_wait() {
    asm volatile("cp.async.wait_group %0;" :: "n"(N) : "memory");
}
__device__ __forceinline__ void ldmx4(uint32_t* r, uint32_t addr) {
    asm volatile("ldmatrix.sync.aligned.m8n8.x4.shared.b16 {%0,%1,%2,%3}, [%4];"
                 : "=r"(r[0]), "=r"(r[1]), "=r"(r[2]), "=r"(r[3]) : "r"(addr));
}
__device__ __forceinline__ void mma_bf16(float* c, const uint32_t* a, uint32_t b0, uint32_t b1) {
    asm volatile("mma.sync.aligned.m16n8k16.row.col.f32.bf16.bf16.f32 "
                 "{%0,%1,%2,%3}, {%4,%5,%6,%7}, {%8,%9}, {%0,%1,%2,%3};"
                 : "+f"(c[0]), "+f"(c[1]), "+f"(c[2]), "+f"(c[3])
                 : "r"(a[0]), "r"(a[1]), "r"(a[2]), "r"(a[3]), "r"(b0), "r"(b1));
}
__device__ __forceinline__ void mma_f16(float* c, const uint32_t* a, uint32_t b0, uint32_t b1) {
    asm volatile("mma.sync.aligned.m16n8k16.row.col.f32.f16.f16.f32 "
                 "{%0,%1,%2,%3}, {%4,%5,%6,%7}, {%8,%9}, {%0,%1,%2,%3};"
                 : "+f"(c[0]), "+f"(c[1]), "+f"(c[2]), "+f"(c[3])
                 : "r"(a[0]), "r"(a[1]), "r"(a[2]), "r"(a[3]), "r"(b0), "r"(b1));
}
__device__ __forceinline__ void split2(float x, __nv_bfloat16& h, __nv_bfloat16& l) {
    h = __float2bfloat16(x);
    l = __float2bfloat16(x - __bfloat162float(h));
}
__device__ __forceinline__ float wred_max(float v) {
#pragma unroll
    for (int o = 16; o; o >>= 1) v = fmaxf(v, __shfl_xor_sync(0xFFFFFFFFu, v, o));
    return v;
}
__device__ __forceinline__ float wred_sum(float v) {
#pragma unroll
    for (int o = 16; o; o >>= 1) v += __shfl_xor_sync(0xFFFFFFFFu, v, o);
    return v;
}

struct alignas(8)  BF4 { __nv_bfloat16 v[4]; };

// ---------------- merged elementwise split + relenc --------------------------
__global__ __launch_bounds__(256) void split_all(
    const float* __restrict__ q, const float* __restrict__ k, const float* __restrict__ v,
    const float* __restrict__ wq, const float* __restrict__ wke, const float* __restrict__ wkr,
    const float* __restrict__ wv, const float* __restrict__ wf)
{
    int z = blockIdx.z;
    if (z == 8) {   // relative positional encoding (+ headmax init)
        if (blockIdx.x == 0 && threadIdx.x < NH) g_headmax[threadIdx.x] = 0;
        long i = ((long)blockIdx.x * 256 + threadIdx.x) * 4;
        if (i >= (long)SEQ * DM) return;
        int f = (int)(i / DM), c0 = (int)(i % DM);
        float p = (float)(SEQ - 1 - f);
        BF4 h, l;
#pragma unroll
        for (int t = 0; t < 4; t++) {
            int c = c0 + t;
            float e  = (float)(c & ~1) * (1.0f / (float)DM);
            float dv = exp2f(-e * 13.287712379549449f);    // log2(10000)
            float ang = p * dv;
            float s, cs; sincosf(ang, &s, &cs);
            split2((c & 1) ? cs : s, h.v[t], l.v[t]);
        }
        *(BF4*)(g_re_hi + i) = h;
        *(BF4*)(g_re_lo + i) = l;
        return;
    }
    long n = (z < 3) ? (long)SEQ * DM : (long)DM * DM;
    long i = ((long)blockIdx.x * 256 + threadIdx.x) * 4;
    if (i >= n) return;
    const float* src; __nv_bfloat16 *dh, *dl;
    switch (z) {
        case 0: src = q;   dh = g_xq_hi; dl = g_xq_lo; break;
        case 1: src = k;   dh = g_xk_hi; dl = g_xk_lo; break;
        case 2: src = v;   dh = g_xv_hi; dl = g_xv_lo; break;
        case 3: src = wq;  dh = g_wq_hi;  dl = g_wq_lo;  break;
        case 4: src = wke; dh = g_wke_hi; dl = g_wke_lo; break;
        case 5: src = wkr; dh = g_wkr_hi; dl = g_wkr_lo; break;
        case 6: src = wv;  dh = g_wv_hi;  dl = g_wv_lo;  break;
        default: src = wf; dh = g_wf_hi;  dl = g_wf_lo;  break;
    }
    float4 x = *(const float4*)(src + i);
    BF4 h, l;
    split2(x.x, h.v[0], l.v[0]); split2(x.y, h.v[1], l.v[1]);
    split2(x.z, h.v[2], l.v[2]); split2(x.w, h.v[3], l.v[3]);
    *(BF4*)(dh + i) = h;
    *(BF4*)(dl + i) = l;
}

// ---------------- split-bf16 HMMA GEMM core (projections / final) ------------
#define EPI_GELU   1
#define EPI_HALF   6
#define EPI_DUAL16 7
#define EPI_HALFT  8

#define RS 80            // bf16 smem row stride in bytes (40 bf16)

template <int BN>
__device__ __forceinline__ void gemm_core(
    const __nv_bfloat16* __restrict__ Ahi, const __nv_bfloat16* __restrict__ Alo, int lda,
    const __nv_bfloat16* __restrict__ Bhi, const __nv_bfloat16* __restrict__ Blo, int ldb,
    int K, float alpha, int epi,
    float* __restrict__ C, int ldc,
    int ldo,
    __half* __restrict__ H1, __half* __restrict__ H2,
    const float* __restrict__ b1, const float* __restrict__ b2)
{
    constexpr int WN   = BN / 2;
    constexpr int NJ   = WN / 8;
    constexpr int NH32 = WN / 32;
    constexpr int ABF  = 128 * RS;
    constexpr int BB   = BN * RS;
    constexpr int OFF_BHI = 2 * ABF;
    constexpr int STAGE   = 2 * ABF + 2 * BB;

    extern __shared__ char smem[];
    uint32_t sb = smem_u32(smem);

    int tid  = threadIdx.x;
    int lane = tid & 31;
    int w    = tid >> 5;
    int wm   = w >> 1;
    int wn   = w & 1;
    int m0   = blockIdx.y * 128;
    int n0   = blockIdx.x * BN;

    float acc[2][NJ][4];
#pragma unroll
    for (int mi = 0; mi < 2; mi++)
#pragma unroll
        for (int nj = 0; nj < NJ; nj++)
#pragma unroll
            for (int q = 0; q < 4; q++) acc[mi][nj][q] = 0.0f;

    const int nc = K >> 5;

    auto load_stage = [&](int st, int k0) {
        uint32_t s0 = sb + st * STAGE;
#pragma unroll
        for (int i = 0; i < 2; i++) {
            int idx = tid + i * 256;
            int r = idx >> 2, vv = idx & 3;
            uint32_t so = (uint32_t)(r * RS + vv * 16);
            cp16(s0 + so,       Ahi + (long)(m0 + r) * lda + k0 + vv * 8);
            cp16(s0 + ABF + so, Alo + (long)(m0 + r) * lda + k0 + vv * 8);
        }
#pragma unroll
        for (int i = 0; i < BN / 64; i++) {
            int idx = tid + i * 256;
            int r = idx >> 2, vv = idx & 3;
            uint32_t so = (uint32_t)(r * RS + vv * 16);
            cp16(s0 + OFF_BHI + so,      Bhi + (long)(n0 + r) * ldb + k0 + vv * 8);
            cp16(s0 + OFF_BHI + BB + so, Blo + (long)(n0 + r) * ldb + k0 + vv * 8);
        }
        cp_commit();
    };

    auto compute_stage = [&](int st) {
        uint32_t aB = sb + st * STAGE;
        uint32_t bB = sb + st * STAGE + OFF_BHI;
        uint32_t l15 = (uint32_t)(lane & 15);
        uint32_t lh  = (uint32_t)(lane >> 4);
#pragma unroll
        for (int ks = 0; ks < 2; ks++) {
            uint32_t a_hi[2][4], a_lo[2][4];
#pragma unroll
            for (int mi = 0; mi < 2; mi++) {
                uint32_t ad = aB + (wm * 32 + mi * 16 + l15) * RS + ks * 32 + lh * 16;
                ldmx4(a_hi[mi], ad);
                ldmx4(a_lo[mi], ad + ABF);
            }
#pragma unroll
            for (int nh = 0; nh < NH32; nh++) {
                uint32_t b_hi[2][4], b_lo[2][4];
#pragma unroll
                for (int nt = 0; nt < 2; nt++) {
                    uint32_t bd = bB + (wn * WN + nh * 32 + nt * 16 + l15) * RS + ks * 32 + lh * 16;
                    ldmx4(b_hi[nt], bd);
                    ldmx4(b_lo[nt], bd + BB);
                }
#pragma unroll
                for (int mi = 0; mi < 2; mi++)
#pragma unroll
                    for (int nt = 0; nt < 2; nt++)
#pragma unroll
                        for (int s = 0; s < 2; s++) {
                            int nj = nh * 4 + nt * 2 + s;
                            mma_bf16(acc[mi][nj], a_hi[mi], b_hi[nt][s], b_hi[nt][s + 2]);
                            mma_bf16(acc[mi][nj], a_hi[mi], b_lo[nt][s], b_lo[nt][s + 2]);
                            mma_bf16(acc[mi][nj], a_lo[mi], b_hi[nt][s], b_hi[nt][s + 2]);
                        }
            }
        }
    };

    load_stage(0, 0);
    for (int c = 0; c < nc; c++) {
        if (c + 1 < nc) {
            load_stage((c + 1) & 1, (c + 1) << 5);
            cp_wait<1>();
        } else {
            cp_wait<0>();
        }
        __syncthreads();
        compute_stage(c & 1);
        __syncthreads();
    }

    int rb = m0 + wm * 32 + (lane >> 2);
    int cb = n0 + wn * WN + (lane & 3) * 2;
#pragma unroll
    for (int mi = 0; mi < 2; mi++)
#pragma unroll
        for (int nj = 0; nj < NJ; nj++) {
#pragma unroll
            for (int q = 0; q < 4; q++) {
                int m = rb + mi * 16 + (q >> 1) * 8;
                int n = cb + nj * 8 + (q & 1);
                float x = acc[mi][nj][q] * alpha;
                if (epi == EPI_GELU) {
                    C[(long)m * ldc + n] =
                        0.5f * x * (1.0f + erff(x * 0.70710678118654752440f));
                } else if (epi == EPI_HALF) {
                    H1[(long)m * ldo + n] = __float2half(x);
                } else if (epi == EPI_HALFT) {
                    H1[(long)n * ldo + m] = __float2half(x);
                } else {  // EPI_DUAL16
                    long o = (long)m * ldo + n;
                    H1[o] = __float2half(x + b1[n]);
                    H2[o] = __float2half(x + b2[n]);
                }
            }
        }
}

// ---------------- GEMM wrapper kernels ---------------------------------------
__global__ __launch_bounds__(256) void proj_all(const float* __restrict__ up,
                                                const float* __restrict__ vp) {
    int z = blockIdx.z;
    if (z == 0)
        gemm_core<128>(g_xq_hi, g_xq_lo, DM, g_wq_hi, g_wq_lo, DM,
            DM, 1.0f, EPI_DUAL16, nullptr, 0, DM, g_qu16, g_qv16, up, vp);
    else if (z == 1)
        gemm_core<128>(g_xk_hi, g_xk_lo, DM, g_wke_hi, g_wke_lo, DM,
            DM, 1.0f, EPI_HALF, nullptr, 0, DM, g_k16, nullptr, nullptr, nullptr);
    else if (z == 2)
        gemm_core<128>(g_xv_hi, g_xv_lo, DM, g_wv_hi, g_wv_lo, DM,
            DM, 1.0f, EPI_HALFT, nullptr, 0, SEQ, g_v16T, nullptr, nullptr, nullptr);
    else
        gemm_core<128>(g_re_hi, g_re_lo, DM, g_wkr_hi, g_wkr_lo, DM,
            DM, 1.0f, EPI_HALF, nullptr, 0, DM, g_qr16, nullptr, nullptr, nullptr);
}

// ---------------- stripe-persistent fp16 score kernel ------------------------
// One CTA per (128-row m-stripe, head, mode). A tile loaded once (regs);
// B tiles streamed double-buffered over all 16 n-tiles.
#define SRS 144   // 64 fp16 = 128B data + 16B pad

__global__ __launch_bounds__(256) void score_kernel() {
    extern __shared__ char smem[];
    uint32_t sA = smem_u32(smem);
    uint32_t sB = sA + 128 * SRS;

    int tid = threadIdx.x, lane = tid & 31, w = tid >> 5;
    int wm = w >> 1, wn = w & 1;
    int m0 = blockIdx.x * 128;
    int z = blockIdx.y, h = z & (NH - 1), mode = z >> 4;

    const __half* Ag = (mode ? g_qv16 : g_qu16) + h * DH;
    const __half* Bg = (mode ? g_qr16 : g_k16)  + h * DH;
    __half* dst = (mode ? g_bds : g_ac) + (long)h * SS;

    // A stripe + B tile 0
#pragma unroll
    for (int i = 0; i < 4; i++) {
        int idx = tid + i * 256;
        int r = idx >> 3, v = idx & 7;
        cp16(sA + r * SRS + v * 16, Ag + (long)(m0 + r) * DM + v * 8);
        cp16(sB + r * SRS + v * 16, Bg + (long)r * DM + v * 8);
    }
    cp_commit();

    uint32_t l15 = (uint32_t)(lane & 15);
    uint32_t lh  = (uint32_t)(lane >> 4);
    uint32_t a[2][4][4];
    const float al = 1.0f / 32.0f;     // 1/sqrt(D_MODEL)
    int rb = m0 + wm * 32 + (lane >> 2);
    int cb_l = wn * 64 + (lane & 3) * 2;

    for (int nt = 0; nt < 16; nt++) {
        if (nt + 1 < 16) {
            uint32_t s0 = sB + ((nt + 1) & 1) * (128 * SRS);
            int n0 = (nt + 1) * 128;
#pragma unroll
            for (int i = 0; i < 4; i++) {
                int idx = tid + i * 256;
                int r = idx >> 3, v = idx & 7;
                cp16(s0 + r * SRS + v * 16, Bg + (long)(n0 + r) * DM + v * 8);
            }
            cp_commit();
            cp_wait<1>();
        } else {
            cp_wait<0>();
        }
        __syncthreads();

        if (nt == 0) {
#pragma unroll
            for (int mi = 0; mi < 2; mi++)
#pragma unroll
                for (int ks = 0; ks < 4; ks++)
                    ldmx4(a[mi][ks], sA + (wm * 32 + mi * 16 + l15) * SRS + ks * 32 + lh * 16);
        }

        uint32_t bB = sB + (nt & 1) * (128 * SRS);
        float acc[2][8][4];
#pragma unroll
        for (int mi = 0; mi < 2; mi++)
#pragma unroll
            for (int nj = 0; nj < 8; nj++)
#pragma unroll
                for (int q = 0; q < 4; q++) acc[mi][nj][q] = 0.0f;

#pragma unroll
        for (int ks = 0; ks < 4; ks++) {
#pragma unroll
            for (int nh = 0; nh < 2; nh++) {
                uint32_t b[2][4];
#pragma unroll
                for (int bt = 0; bt < 2; bt++)
                    ldmx4(b[bt], bB + (wn * 64 + nh * 32 + bt * 16 + l15) * SRS + ks * 32 + lh * 16);
#pragma unroll
                for (int mi = 0; mi < 2; mi++)
#pragma unroll
                    for (int bt = 0; bt < 2; bt++)
#pragma unroll
                        for (int s = 0; s < 2; s++)
                            mma_f16(acc[mi][nh * 4 + bt * 2 + s], a[mi][ks], b[bt][s], b[bt][s + 2]);
            }
        }
        __syncthreads();

        int cb = nt * 128 + cb_l;
#pragma unroll
        for (int mi = 0; mi < 2; mi++)
#pragma unroll
            for (int nj = 0; nj < 8; nj++) {
                int m = rb + mi * 16;
                int n = cb + nj * 8;
                *(__half2*)(dst + (long)m * SEQ + n) =
                    __floats2half2_rn(acc[mi][nj][0] * al, acc[mi][nj][1] * al);
                *(__half2*)(dst + (long)(m + 8) * SEQ + n) =
                    __floats2half2_rn(acc[mi][nj][2] * al, acc[mi][nj][3] * al);
            }
    }
}

// ---------------- fp16 einsum: out1 = w16 @ v16T^T ---------------------------
#define ESTAGE (128 * SRS + 64 * SRS)

__global__ __launch_bounds__(256) void einsum16_k() {
    extern __shared__ char smem[];
    uint32_t sb = smem_u32(smem);

    int tid = threadIdx.x, lane = tid & 31, w = tid >> 5;
    int wm = w >> 1, wn = w & 1;
    int m0 = blockIdx.y * 128;
    int h  = blockIdx.z;

    const __half* A = g_w16  + (long)h * SS;        // 2048 x 2048
    const __half* B = g_v16T + (long)h * DH * SEQ;  // 64 x 2048

    float acc[2][4][4];
#pragma unroll
    for (int mi = 0; mi < 2; mi++)
#pragma unroll
        for (int nj = 0; nj < 4; nj++)
#pragma unroll
            for (int q = 0; q < 4; q++) acc[mi][nj][q] = 0.0f;

    auto load_stage = [&](int st, int k0) {
        uint32_t s0 = sb + st * ESTAGE;
#pragma unroll
        for (int i = 0; i < 4; i++) {
            int idx = tid + i * 256;
            int r = idx >> 3, v = idx & 7;
            cp16(s0 + r * SRS + v * 16, A + (long)(m0 + r) * SEQ + k0 + v * 8);
        }
#pragma unroll
        for (int i = 0; i < 2; i++) {
            int idx = tid + i * 256;
            int r = idx >> 3, v = idx & 7;
            cp16(s0 + 128 * SRS + r * SRS + v * 16, B + (long)r * SEQ + k0 + v * 8);
        }
        cp_commit();
    };

    auto compute_stage = [&](int st) {
        uint32_t aB = sb + st * ESTAGE;
        uint32_t bB = aB + 128 * SRS;
        uint32_t l15 = (uint32_t)(lane & 15);
        uint32_t lh  = (uint32_t)(lane >> 4);
#pragma unroll
        for (int ks = 0; ks < 4; ks++) {
            uint32_t a[2][4];
#pragma unroll
            for (int mi = 0; mi < 2; mi++)
                ldmx4(a[mi], aB + (wm * 32 + mi * 16 + l15) * SRS + ks * 32 + lh * 16);
            uint32_t b[2][4];
#pragma unroll
            for (int nt = 0; nt < 2; nt++)
                ldmx4(b[nt], bB + (wn * 32 + nt * 16 + l15) * SRS + ks * 32 + lh * 16);
#pragma unroll
            for (int mi = 0; mi < 2; mi++)
#pragma unroll
                for (int nt = 0; nt < 2; nt++)
#pragma unroll
                    for (int s = 0; s < 2; s++)
                        mma_f16(acc[mi][nt * 2 + s], a[mi], b[nt][s], b[nt][s + 2]);
        }
    };

    load_stage(0, 0);
    const int nc = SEQ / 64;
    for (int c = 0; c < nc; c++) {
        if (c + 1 < nc) {
            load_stage((c + 1) & 1, (c + 1) * 64);
            cp_wait<1>();
        } else {
            cp_wait<0>();
        }
        __syncthreads();
        compute_stage(c & 1);
        __syncthreads();
    }

    int rb = m0 + wm * 32 + (lane >> 2);
    int cb = h * DH + wn * 32 + (lane & 3) * 2;
#pragma unroll
    for (int mi = 0; mi < 2; mi++)
#pragma unroll
        for (int nj = 0; nj < 4; nj++)
#pragma unroll
            for (int q = 0; q < 4; q++) {
                int m = rb + mi * 16 + (q >> 1) * 8;
                int n = cb + nj * 8 + (q & 1);
                __nv_bfloat16 hh, ll; split2(acc[mi][nj][q], hh, ll);
                long o = (long)m * DM + n;
                g_o1_hi[o] = hh; g_o1_lo[o] = ll;
            }
}

__global__ __launch_bounds__(256) void final_k(float* __restrict__ out) {
    gemm_core<128>(g_o1_hi, g_o1_lo, DM, g_wf_hi, g_wf_lo, DM,
        DM, 1.0f, EPI_GELU, out, DM, 0, nullptr, nullptr, nullptr, nullptr);
}

// ---------------- fused gather-shift + mask + softmax ------------------------
__global__ __launch_bounds__(256) void softmax_kernel(float* __restrict__ w,
                                                      const float* __restrict__ mask) {
    int s = blockIdx.x, h = blockIdx.y;
    long base = ((long)h * SEQ + s) * SEQ;
    const __half* hat = g_bds + (long)h * SS;
    __shared__ float red[8], red2[8];
    int tid = threadIdx.x;
    int lane = tid & 31, wid = tid >> 5;
    int j0 = tid * 8;

    // rel-shift gather geometry (two contiguous runs per row)
    long flat0 = (long)s * SEQ + (SEQ - 1);
    int sp0 = (int)(flat0 / (SEQ + 1));
    int jp0 = (int)(flat0 - (long)sp0 * (SEQ + 1));
    int jwrap = (SEQ + 1) - jp0;
    long base1 = (long)sp0 * SEQ + jp0;
    long base2 = (long)(sp0 + 1) * SEQ - jwrap;

    uint4 acr = *(const uint4*)(g_ac + base + j0);
    float4 mk0 = *(const float4*)(mask + (long)s * SEQ + j0);
    float4 mk1 = *(const float4*)(mask + (long)s * SEQ + j0 + 4);

    float vals[8];
    {
        const __half2* ah = (const __half2*)&acr;
#pragma unroll
        for (int i = 0; i < 4; i++) {
            float2 a2 = __half22float2(ah[i]);
            vals[2 * i]     = a2.x;
            vals[2 * i + 1] = a2.y;
        }
        const float* mka = (const float*)&mk0;
        const float* mkb = (const float*)&mk1;
#pragma unroll
        for (int i = 0; i < 4; i++) vals[i]     += mka[i];
#pragma unroll
        for (int i = 0; i < 4; i++) vals[4 + i] += mkb[i];
#pragma unroll
        for (int i = 0; i < 8; i++) {
            int j = j0 + i;
            if (j != s + 1)
                vals[i] += __half2float(hat[(j < jwrap ? base1 : base2) + j]);
        }
    }

    float vmax = -3.0e38f;
#pragma unroll
    for (int i = 0; i < 8; i++) vmax = fmaxf(vmax, vals[i]);
    vmax = wred_max(vmax);
    if (lane == 0) red[wid] = vmax;
    __syncthreads();
    vmax = red[0];
#pragma unroll
    for (int i = 1; i < 8; i++) vmax = fmaxf(vmax, red[i]);

    float sum = 0.0f;
#pragma unroll
    for (int i = 0; i < 8; i++) {
        vals[i] = expf(vals[i] - vmax);
        sum += vals[i];
    }
    sum = wred_sum(sum);
    if (lane == 0) red2[wid] = sum;
    __syncthreads();
    sum = red2[0];
#pragma unroll
    for (int i = 1; i < 8; i++) sum += red2[i];
    float inv = 1.0f / sum;

    float4 o0 = make_float4(vals[0] * inv, vals[1] * inv, vals[2] * inv, vals[3] * inv);
    float4 o1 = make_float4(vals[4] * inv, vals[5] * inv, vals[6] * inv, vals[7] * inv);
    *(float4*)(w + base + j0)     = o0;
    *(float4*)(w + base + j0 + 4) = o1;

    uint2 h16;
    __half2* hp = (__half2*)&h16;
    hp[0] = __floats2half2_rn(o0.x, o0.y);
    hp[1] = __floats2half2_rn(o0.z, o0.w);
    *(uint2*)(g_w16 + base + j0) = h16;
    hp[0] = __floats2half2_rn(o1.x, o1.y);
    hp[1] = __floats2half2_rn(o1.z, o1.w);
    *(uint2*)(g_w16 + base + j0 + 4) = h16;

    if (tid == 0) atomicMax(&g_headmax[h], __float_as_int(inv));
}

__global__ void loss_kernel(float* __restrict__ out) {
    if (threadIdx.x == 0) {
        float s = 0.0f;
        for (int h = 0; h < NH; h++) s += __int_as_float(g_headmax[h]);
        out[(long)SEQ * DM + (long)NH * SS] = s / (float)NH;
    }
}

// ---------------- launcher ---------------------------------------------------
extern "C" void kernel_launch(void* const* d_in, const int* in_sizes, int n_in,
                              void* d_out, int out_size) {
    (void)in_sizes; (void)n_in; (void)out_size;
    const float* query = (const float*)d_in[0];
    const float* key   = (const float*)d_in[1];
    const float* value = (const float*)d_in[2];
    const float* mask  = (const float*)d_in[3];
    const float* Wq    = (const float*)d_in[4];
    const float* Wke   = (const float*)d_in[5];
    const float* Wkr   = (const float*)d_in[6];
    const float* Wv    = (const float*)d_in[7];
    const float* Wf    = (const float*)d_in[8];
    const float* up    = (const float*)d_in[9];
    const float* vp    = (const float*)d_in[10];

    float* out = (float*)d_out;
    float* w   = out + (long)SEQ * DM;

    constexpr int SMEM_BF = 2 * (2 * 128 * RS + 2 * 128 * RS);   // 81920
    constexpr int SMEM_E  = 2 * ESTAGE;                          // 55296
    constexpr int SMEM_S  = 3 * 128 * SRS;                       // 55296
    cudaFuncSetAttribute(proj_all,     cudaFuncAttributeMaxDynamicSharedMemorySize, SMEM_BF);
    cudaFuncSetAttribute(final_k,      cudaFuncAttributeMaxDynamicSharedMemorySize, SMEM_BF);
    cudaFuncSetAttribute(einsum16_k,   cudaFuncAttributeMaxDynamicSharedMemorySize, SMEM_E);
    cudaFuncSetAttribute(score_kernel, cudaFuncAttributeMaxDynamicSharedMemorySize, SMEM_S);

    // 1. merged relenc + input/weight splits (one launch)
    split_all<<<dim3(SEQ * DM / 1024, 1, 9), 256>>>(query, key, value, Wq, Wke, Wkr, Wv, Wf);

    // 2. all projections, one launch
    proj_all<<<dim3(DM / 128, SEQ / 128, 4), 256, SMEM_BF>>>(up, vp);

    // 3. scores: stripe-persistent fp16 (y<16: A_C; y>=16: B_D_hat)
    score_kernel<<<dim3(SEQ / 128, 2 * NH), 256, SMEM_S>>>();

    // 4. fused gather-shift + mask + softmax; emits w (fp32) + w16 (fp16)
    softmax_kernel<<<dim3(SEQ, NH), 256>>>(w, mask);

    // 5. fp16 single-pass einsum -> o1 (bf16 hi/lo)
    einsum16_k<<<dim3(1, SEQ / 128, NH), 256, SMEM_E>>>();

    // 6. final projection + exact GELU
    final_k<<<dim3(DM / 128, SEQ / 128, 1), 256, SMEM_BF>>>(out);

    // 7. loss scalar
    loss_kernel<<<1, 1>>>(out);
}

// round 10
// speedup vs baseline: 4.0667x; 1.0368x over previous
#include <cuda_runtime.h>
#include <cuda_bf16.h>
#include <cuda_fp16.h>
#include <math.h>
#include <stdint.h>

#define SEQ 2048
#define DM  1024
#define NH  16
#define DH  64
#define SS  ((long)SEQ * SEQ)

// ---------------- scratch (device globals; no allocations allowed) ----------
__device__ __half g_bds[(size_t)NH * SEQ * SEQ];            // B_D_hat (unshifted), fp16
__device__ __half g_ac[(size_t)NH * SEQ * SEQ];             // A_C scores, fp16
__device__ __half g_w16[(size_t)NH * SEQ * SEQ];            // softmax weights, fp16

// fp16 inputs/weights for the score-path projections
__device__ __half g_xq16[SEQ * DM], g_xkey16[SEQ * DM], g_re16[SEQ * DM];
__device__ __half g_wq16[DM * DM], g_wke16[DM * DM], g_wkr16[DM * DM];

// split-bf16 operands for the output-path GEMMs
__device__ __nv_bfloat16 g_xv_hi[SEQ * DM], g_xv_lo[SEQ * DM];
__device__ __nv_bfloat16 g_wv_hi[DM * DM],  g_wv_lo[DM * DM];
__device__ __nv_bfloat16 g_wf_hi[DM * DM],  g_wf_lo[DM * DM];

__device__ __half g_qu16[SEQ * DM], g_qv16[SEQ * DM];       // fp16 score operands
__device__ __half g_k16[SEQ * DM],  g_qr16[SEQ * DM];

__device__ __half g_v16T[DM * SEQ];                          // [h*64+d][f], fp16
__device__ __nv_bfloat16 g_o1_hi[SEQ * DM], g_o1_lo[SEQ * DM];

__device__ int g_headmax[NH];

// ---------------- helpers ----------------------------------------------------
__device__ __forceinline__ uint32_t smem_u32(const void* p) {
    uint32_t a;
    asm("{ .reg .u64 t; cvta.to.shared.u64 t, %1; cvt.u32.u64 %0, t; }" : "=r"(a) : "l"(p));
    return a;
}
__device__ __forceinline__ void cp16(uint32_t s, const void* g) {
    asm volatile("cp.async.cg.shared.global [%0], [%1], 16;" :: "r"(s), "l"(g));
}
__device__ __forceinline__ void cp_commit() {
    asm volatile("cp.async.commit_group;" ::: "memory");
}
template <int N>
__device__ __forceinline__ void cp_wait() {
    asm volatile("cp.async.wait_group %0;" :: "n"(N) : "memory");
}
__device__ __forceinline__ void ldmx4(uint32_t* r, uint32_t addr) {
    asm volatile("ldmatrix.sync.aligned.m8n8.x4.shared.b16 {%0,%1,%2,%3}, [%4];"
                 : "=r"(r[0]), "=r"(r[1]), "=r"(r[2]), "=r"(r[3]) : "r"(addr));
}
__device__ __forceinline__ void mma_bf16(float* c, const uint32_t* a, uint32_t b0, uint32_t b1) {
    asm volatile("mma.sync.aligned.m16n8k16.row.col.f32.bf16.bf16.f32 "
                 "{%0,%1,%2,%3}, {%4,%5,%6,%7}, {%8,%9}, {%0,%1,%2,%3};"
                 : "+f"(c[0]), "+f"(c[1]), "+f"(c[2]), "+f"(c[3])
                 : "r"(a[0]), "r"(a[1]), "r"(a[2]), "r"(a[3]), "r"(b0), "r"(b1));
}
__device__ __forceinline__ void mma_f16(float* c, const uint32_t* a, uint32_t b0, uint32_t b1) {
    asm volatile("mma.sync.aligned.m16n8k16.row.col.f32.f16.f16.f32 "
                 "{%0,%1,%2,%3}, {%4,%5,%6,%7}, {%8,%9}, {%0,%1,%2,%3};"
                 : "+f"(c[0]), "+f"(c[1]), "+f"(c[2]), "+f"(c[3])
                 : "r"(a[0]), "r"(a[1]), "r"(a[2]), "r"(a[3]), "r"(b0), "r"(b1));
}
__device__ __forceinline__ void split2(float x, __nv_bfloat16& h, __nv_bfloat16& l) {
    h = __float2bfloat16(x);
    l = __float2bfloat16(x - __bfloat162float(h));
}
__device__ __forceinline__ float wred_max(float v) {
#pragma unroll
    for (int o = 16; o; o >>= 1) v = fmaxf(v, __shfl_xor_sync(0xFFFFFFFFu, v, o));
    return v;
}
__device__ __forceinline__ float wred_sum(float v) {
#pragma unroll
    for (int o = 16; o; o >>= 1) v += __shfl_xor_sync(0xFFFFFFFFu, v, o);
    return v;
}

struct alignas(8) BF4 { __nv_bfloat16 v[4]; };
struct alignas(8) H4  { __half v[4]; };

// ---------------- merged elementwise convert + relenc ------------------------
__global__ __launch_bounds__(256) void split_all(
    const float* __restrict__ q, const float* __restrict__ k, const float* __restrict__ v,
    const float* __restrict__ wq, const float* __restrict__ wke, const float* __restrict__ wkr,
    const float* __restrict__ wv, const float* __restrict__ wf)
{
    int z = blockIdx.z;
    long i = ((long)blockIdx.x * 256 + threadIdx.x) * 4;
    if (z == 8) {   // relative positional encoding, fp16 (+ headmax init)
        if (blockIdx.x == 0 && threadIdx.x < NH) g_headmax[threadIdx.x] = 0;
        if (i >= (long)SEQ * DM) return;
        int f = (int)(i / DM), c0 = (int)(i % DM);
        float p = (float)(SEQ - 1 - f);
        H4 o;
#pragma unroll
        for (int t = 0; t < 4; t++) {
            int c = c0 + t;
            float e  = (float)(c & ~1) * (1.0f / (float)DM);
            float dv = exp2f(-e * 13.287712379549449f);    // log2(10000)
            float ang = p * dv;
            float s, cs; sincosf(ang, &s, &cs);
            o.v[t] = __float2half((c & 1) ? cs : s);
        }
        *(H4*)(g_re16 + i) = o;
        return;
    }
    long n = (z < 3) ? (long)SEQ * DM : (long)DM * DM;
    if (i >= n) return;
    const float* src; __half* d16 = nullptr; __nv_bfloat16 *dh = nullptr, *dl = nullptr;
    switch (z) {
        case 0: src = q;   d16 = g_xq16;   break;
        case 1: src = k;   d16 = g_xkey16; break;
        case 2: src = v;   dh = g_xv_hi; dl = g_xv_lo; break;
        case 3: src = wq;  d16 = g_wq16;  break;
        case 4: src = wke; d16 = g_wke16; break;
        case 5: src = wkr; d16 = g_wkr16; break;
        case 6: src = wv;  dh = g_wv_hi; dl = g_wv_lo; break;
        default: src = wf; dh = g_wf_hi; dl = g_wf_lo; break;
    }
    float4 x = *(const float4*)(src + i);
    if (d16) {
        H4 o;
        o.v[0] = __float2half(x.x); o.v[1] = __float2half(x.y);
        o.v[2] = __float2half(x.z); o.v[3] = __float2half(x.w);
        *(H4*)(d16 + i) = o;
    } else {
        BF4 h, l;
        split2(x.x, h.v[0], l.v[0]); split2(x.y, h.v[1], l.v[1]);
        split2(x.z, h.v[2], l.v[2]); split2(x.w, h.v[3], l.v[3]);
        *(BF4*)(dh + i) = h;
        *(BF4*)(dl + i) = l;
    }
}

// ---------------- split-bf16 HMMA GEMM core (V projection / final) -----------
#define EPI_GELU   1
#define EPI_HALFT  8

#define RS 80            // bf16 smem row stride in bytes (40 bf16)

template <int BN>
__device__ __forceinline__ void gemm_core(
    const __nv_bfloat16* __restrict__ Ahi, const __nv_bfloat16* __restrict__ Alo, int lda,
    const __nv_bfloat16* __restrict__ Bhi, const __nv_bfloat16* __restrict__ Blo, int ldb,
    int K, int epi,
    float* __restrict__ C, int ldc,
    int ldo, __half* __restrict__ H1)
{
    constexpr int WN   = BN / 2;
    constexpr int NJ   = WN / 8;
    constexpr int NH32 = WN / 32;
    constexpr int ABF  = 128 * RS;
    constexpr int BB   = BN * RS;
    constexpr int OFF_BHI = 2 * ABF;
    constexpr int STAGE   = 2 * ABF + 2 * BB;

    extern __shared__ char smem[];
    uint32_t sb = smem_u32(smem);

    int tid  = threadIdx.x;
    int lane = tid & 31;
    int w    = tid >> 5;
    int wm   = w >> 1;
    int wn   = w & 1;
    int m0   = blockIdx.y * 128;
    int n0   = blockIdx.x * BN;

    float acc[2][NJ][4];
#pragma unroll
    for (int mi = 0; mi < 2; mi++)
#pragma unroll
        for (int nj = 0; nj < NJ; nj++)
#pragma unroll
            for (int q = 0; q < 4; q++) acc[mi][nj][q] = 0.0f;

    const int nc = K >> 5;

    auto load_stage = [&](int st, int k0) {
        uint32_t s0 = sb + st * STAGE;
#pragma unroll
        for (int i = 0; i < 2; i++) {
            int idx = tid + i * 256;
            int r = idx >> 2, vv = idx & 3;
            uint32_t so = (uint32_t)(r * RS + vv * 16);
            cp16(s0 + so,       Ahi + (long)(m0 + r) * lda + k0 + vv * 8);
            cp16(s0 + ABF + so, Alo + (long)(m0 + r) * lda + k0 + vv * 8);
        }
#pragma unroll
        for (int i = 0; i < BN / 64; i++) {
            int idx = tid + i * 256;
            int r = idx >> 2, vv = idx & 3;
            uint32_t so = (uint32_t)(r * RS + vv * 16);
            cp16(s0 + OFF_BHI + so,      Bhi + (long)(n0 + r) * ldb + k0 + vv * 8);
            cp16(s0 + OFF_BHI + BB + so, Blo + (long)(n0 + r) * ldb + k0 + vv * 8);
        }
        cp_commit();
    };

    auto compute_stage = [&](int st) {
        uint32_t aB = sb + st * STAGE;
        uint32_t bB = sb + st * STAGE + OFF_BHI;
        uint32_t l15 = (uint32_t)(lane & 15);
        uint32_t lh  = (uint32_t)(lane >> 4);
#pragma unroll
        for (int ks = 0; ks < 2; ks++) {
            uint32_t a_hi[2][4], a_lo[2][4];
#pragma unroll
            for (int mi = 0; mi < 2; mi++) {
                uint32_t ad = aB + (wm * 32 + mi * 16 + l15) * RS + ks * 32 + lh * 16;
                ldmx4(a_hi[mi], ad);
                ldmx4(a_lo[mi], ad + ABF);
            }
#pragma unroll
            for (int nh = 0; nh < NH32; nh++) {
                uint32_t b_hi[2][4], b_lo[2][4];
#pragma unroll
                for (int nt = 0; nt < 2; nt++) {
                    uint32_t bd = bB + (wn * WN + nh * 32 + nt * 16 + l15) * RS + ks * 32 + lh * 16;
                    ldmx4(b_hi[nt], bd);
                    ldmx4(b_lo[nt], bd + BB);
                }
#pragma unroll
                for (int mi = 0; mi < 2; mi++)
#pragma unroll
                    for (int nt = 0; nt < 2; nt++)
#pragma unroll
                        for (int s = 0; s < 2; s++) {
                            int nj = nh * 4 + nt * 2 + s;
                            mma_bf16(acc[mi][nj], a_hi[mi], b_hi[nt][s], b_hi[nt][s + 2]);
                            mma_bf16(acc[mi][nj], a_hi[mi], b_lo[nt][s], b_lo[nt][s + 2]);
                            mma_bf16(acc[mi][nj], a_lo[mi], b_hi[nt][s], b_hi[nt][s + 2]);
                        }
            }
        }
    };

    load_stage(0, 0);
    for (int c = 0; c < nc; c++) {
        if (c + 1 < nc) {
            load_stage((c + 1) & 1, (c + 1) << 5);
            cp_wait<1>();
        } else {
            cp_wait<0>();
        }
        __syncthreads();
        compute_stage(c & 1);
        __syncthreads();
    }

    int rb = m0 + wm * 32 + (lane >> 2);
    int cb = n0 + wn * WN + (lane & 3) * 2;
#pragma unroll
    for (int mi = 0; mi < 2; mi++)
#pragma unroll
        for (int nj = 0; nj < NJ; nj++) {
#pragma unroll
            for (int q = 0; q < 4; q++) {
                int m = rb + mi * 16 + (q >> 1) * 8;
                int n = cb + nj * 8 + (q & 1);
                float x = acc[mi][nj][q];
                if (epi == EPI_GELU) {
                    C[(long)m * ldc + n] =
                        0.5f * x * (1.0f + erff(x * 0.70710678118654752440f));
                } else {  // EPI_HALFT
                    H1[(long)n * ldo + m] = __float2half(x);
                }
            }
        }
}

__global__ __launch_bounds__(256) void projV() {
    gemm_core<128>(g_xv_hi, g_xv_lo, DM, g_wv_hi, g_wv_lo, DM,
        DM, EPI_HALFT, nullptr, 0, SEQ, g_v16T);
}

__global__ __launch_bounds__(256) void final_k(float* __restrict__ out) {
    gemm_core<64>(g_o1_hi, g_o1_lo, DM, g_wf_hi, g_wf_lo, DM,
        DM, EPI_GELU, out, DM, 0, nullptr);
}

// ---------------- fp16 single-pass projection GEMM (q/k/rel) ------------------
#define SRS 144   // 64 fp16 = 128B data + 16B pad
#define P16_STAGE (2 * 128 * SRS)

__global__ __launch_bounds__(256) void proj16(const float* __restrict__ up,
                                              const float* __restrict__ vp) {
    extern __shared__ char smem[];
    uint32_t sb = smem_u32(smem);

    int tid = threadIdx.x, lane = tid & 31, w = tid >> 5;
    int wm = w >> 1, wn = w & 1;
    int m0 = blockIdx.y * 128, n0 = blockIdx.x * 128;
    int z = blockIdx.z;

    const __half *Ag, *Bg;
    __half *H1, *H2 = nullptr;
    if (z == 0)      { Ag = g_xq16;   Bg = g_wq16;  H1 = g_qu16; H2 = g_qv16; }
    else if (z == 1) { Ag = g_xkey16; Bg = g_wke16; H1 = g_k16; }
    else             { Ag = g_re16;   Bg = g_wkr16; H1 = g_qr16; }

    float acc[2][8][4];
#pragma unroll
    for (int mi = 0; mi < 2; mi++)
#pragma unroll
        for (int nj = 0; nj < 8; nj++)
#pragma unroll
            for (int q = 0; q < 4; q++) acc[mi][nj][q] = 0.0f;

    auto load_stage = [&](int st, int k0) {
        uint32_t s0 = sb + st * P16_STAGE;
#pragma unroll
        for (int i = 0; i < 4; i++) {
            int idx = tid + i * 256;
            int r = idx >> 3, v = idx & 7;
            cp16(s0 + r * SRS + v * 16,             Ag + (long)(m0 + r) * DM + k0 + v * 8);
            cp16(s0 + 128 * SRS + r * SRS + v * 16, Bg + (long)(n0 + r) * DM + k0 + v * 8);
        }
        cp_commit();
    };

    auto compute_stage = [&](int st) {
        uint32_t aB = sb + st * P16_STAGE;
        uint32_t bB = aB + 128 * SRS;
        uint32_t l15 = (uint32_t)(lane & 15);
        uint32_t lh  = (uint32_t)(lane >> 4);
#pragma unroll
        for (int ks = 0; ks < 4; ks++) {
            uint32_t a[2][4];
#pragma unroll
            for (int mi = 0; mi < 2; mi++)
                ldmx4(a[mi], aB + (wm * 32 + mi * 16 + l15) * SRS + ks * 32 + lh * 16);
#pragma unroll
            for (int nh = 0; nh < 2; nh++) {
                uint32_t b[2][4];
#pragma unroll
                for (int bt = 0; bt < 2; bt++)
                    ldmx4(b[bt], bB + (wn * 64 + nh * 32 + bt * 16 + l15) * SRS + ks * 32 + lh * 16);
#pragma unroll
                for (int mi = 0; mi < 2; mi++)
#pragma unroll
                    for (int bt = 0; bt < 2; bt++)
#pragma unroll
                        for (int s = 0; s < 2; s++)
                            mma_f16(acc[mi][nh * 4 + bt * 2 + s], a[mi], b[bt][s], b[bt][s + 2]);
            }
        }
    };

    load_stage(0, 0);
    const int nc = DM / 64;
    for (int c = 0; c < nc; c++) {
        if (c + 1 < nc) {
            load_stage((c + 1) & 1, (c + 1) * 64);
            cp_wait<1>();
        } else {
            cp_wait<0>();
        }
        __syncthreads();
        compute_stage(c & 1);
        __syncthreads();
    }

    int rb = m0 + wm * 32 + (lane >> 2);
    int cb = n0 + wn * 64 + (lane & 3) * 2;
#pragma unroll
    for (int mi = 0; mi < 2; mi++)
#pragma unroll
        for (int nj = 0; nj < 8; nj++) {
            int m = rb + mi * 16;
            int n = cb + nj * 8;
            if (z == 0) {
                float b1n = up[n], b1n1 = up[n + 1];
                float b2n = vp[n], b2n1 = vp[n + 1];
                *(__half2*)(H1 + (long)m * DM + n) =
                    __floats2half2_rn(acc[mi][nj][0] + b1n, acc[mi][nj][1] + b1n1);
                *(__half2*)(H1 + (long)(m + 8) * DM + n) =
                    __floats2half2_rn(acc[mi][nj][2] + b1n, acc[mi][nj][3] + b1n1);
                *(__half2*)(H2 + (long)m * DM + n) =
                    __floats2half2_rn(acc[mi][nj][0] + b2n, acc[mi][nj][1] + b2n1);
                *(__half2*)(H2 + (long)(m + 8) * DM + n) =
                    __floats2half2_rn(acc[mi][nj][2] + b2n, acc[mi][nj][3] + b2n1);
            } else {
                *(__half2*)(H1 + (long)m * DM + n) =
                    __floats2half2_rn(acc[mi][nj][0], acc[mi][nj][1]);
                *(__half2*)(H1 + (long)(m + 8) * DM + n) =
                    __floats2half2_rn(acc[mi][nj][2], acc[mi][nj][3]);
            }
        }
}

// ---------------- stripe-persistent fp16 score kernel ------------------------
__global__ __launch_bounds__(256) void score_kernel() {
    extern __shared__ char smem[];
    uint32_t sA = smem_u32(smem);
    uint32_t sB = sA + 128 * SRS;

    int tid = threadIdx.x, lane = tid & 31, w = tid >> 5;
    int wm = w >> 1, wn = w & 1;
    int m0 = blockIdx.x * 128;
    int z = blockIdx.y, h = z & (NH - 1), mode = z >> 4;

    const __half* Ag = (mode ? g_qv16 : g_qu16) + h * DH;
    const __half* Bg = (mode ? g_qr16 : g_k16)  + h * DH;
    __half* dst = (mode ? g_bds : g_ac) + (long)h * SS;

#pragma unroll
    for (int i = 0; i < 4; i++) {
        int idx = tid + i * 256;
        int r = idx >> 3, v = idx & 7;
        cp16(sA + r * SRS + v * 16, Ag + (long)(m0 + r) * DM + v * 8);
        cp16(sB + r * SRS + v * 16, Bg + (long)r * DM + v * 8);
    }
    cp_commit();

    uint32_t l15 = (uint32_t)(lane & 15);
    uint32_t lh  = (uint32_t)(lane >> 4);
    uint32_t a[2][4][4];
    const float al = 1.0f / 32.0f;     // 1/sqrt(D_MODEL)
    int rb = m0 + wm * 32 + (lane >> 2);
    int cb_l = wn * 64 + (lane & 3) * 2;

    for (int nt = 0; nt < 16; nt++) {
        if (nt + 1 < 16) {
            uint32_t s0 = sB + ((nt + 1) & 1) * (128 * SRS);
            int n0 = (nt + 1) * 128;
#pragma unroll
            for (int i = 0; i < 4; i++) {
                int idx = tid + i * 256;
                int r = idx >> 3, v = idx & 7;
                cp16(s0 + r * SRS + v * 16, Bg + (long)(n0 + r) * DM + v * 8);
            }
            cp_commit();
            cp_wait<1>();
        } else {
            cp_wait<0>();
        }
        __syncthreads();

        if (nt == 0) {
#pragma unroll
            for (int mi = 0; mi < 2; mi++)
#pragma unroll
                for (int ks = 0; ks < 4; ks++)
                    ldmx4(a[mi][ks], sA + (wm * 32 + mi * 16 + l15) * SRS + ks * 32 + lh * 16);
        }

        uint32_t bB = sB + (nt & 1) * (128 * SRS);
        float acc[2][8][4];
#pragma unroll
        for (int mi = 0; mi < 2; mi++)
#pragma unroll
            for (int nj = 0; nj < 8; nj++)
#pragma unroll
                for (int q = 0; q < 4; q++) acc[mi][nj][q] = 0.0f;

#pragma unroll
        for (int ks = 0; ks < 4; ks++) {
#pragma unroll
            for (int nh = 0; nh < 2; nh++) {
                uint32_t b[2][4];
#pragma unroll
                for (int bt = 0; bt < 2; bt++)
                    ldmx4(b[bt], bB + (wn * 64 + nh * 32 + bt * 16 + l15) * SRS + ks * 32 + lh * 16);
#pragma unroll
                for (int mi = 0; mi < 2; mi++)
#pragma unroll
                    for (int bt = 0; bt < 2; bt++)
#pragma unroll
                        for (int s = 0; s < 2; s++)
                            mma_f16(acc[mi][nh * 4 + bt * 2 + s], a[mi][ks], b[bt][s], b[bt][s + 2]);
            }
        }
        __syncthreads();

        int cb = nt * 128 + cb_l;
#pragma unroll
        for (int mi = 0; mi < 2; mi++)
#pragma unroll
            for (int nj = 0; nj < 8; nj++) {
                int m = rb + mi * 16;
                int n = cb + nj * 8;
                *(__half2*)(dst + (long)m * SEQ + n) =
                    __floats2half2_rn(acc[mi][nj][0] * al, acc[mi][nj][1] * al);
                *(__half2*)(dst + (long)(m + 8) * SEQ + n) =
                    __floats2half2_rn(acc[mi][nj][2] * al, acc[mi][nj][3] * al);
            }
    }
}

// ---------------- fp16 einsum: out1 = w16 @ v16T^T ---------------------------
#define ESTAGE (128 * SRS + 64 * SRS)

__global__ __launch_bounds__(256) void einsum16_k() {
    extern __shared__ char smem[];
    uint32_t sb = smem_u32(smem);

    int tid = threadIdx.x, lane = tid & 31, w = tid >> 5;
    int wm = w >> 1, wn = w & 1;
    int m0 = blockIdx.y * 128;
    int h  = blockIdx.z;

    const __half* A = g_w16  + (long)h * SS;        // 2048 x 2048
    const __half* B = g_v16T + (long)h * DH * SEQ;  // 64 x 2048

    float acc[2][4][4];
#pragma unroll
    for (int mi = 0; mi < 2; mi++)
#pragma unroll
        for (int nj = 0; nj < 4; nj++)
#pragma unroll
            for (int q = 0; q < 4; q++) acc[mi][nj][q] = 0.0f;

    auto load_stage = [&](int st, int k0) {
        uint32_t s0 = sb + st * ESTAGE;
#pragma unroll
        for (int i = 0; i < 4; i++) {
            int idx = tid + i * 256;
            int r = idx >> 3, v = idx & 7;
            cp16(s0 + r * SRS + v * 16, A + (long)(m0 + r) * SEQ + k0 + v * 8);
        }
#pragma unroll
        for (int i = 0; i < 2; i++) {
            int idx = tid + i * 256;
            int r = idx >> 3, v = idx & 7;
            cp16(s0 + 128 * SRS + r * SRS + v * 16, B + (long)r * SEQ + k0 + v * 8);
        }
        cp_commit();
    };

    auto compute_stage = [&](int st) {
        uint32_t aB = sb + st * ESTAGE;
        uint32_t bB = aB + 128 * SRS;
        uint32_t l15 = (uint32_t)(lane & 15);
        uint32_t lh  = (uint32_t)(lane >> 4);
#pragma unroll
        for (int ks = 0; ks < 4; ks++) {
            uint32_t a[2][4];
#pragma unroll
            for (int mi = 0; mi < 2; mi++)
                ldmx4(a[mi], aB + (wm * 32 + mi * 16 + l15) * SRS + ks * 32 + lh * 16);
            uint32_t b[2][4];
#pragma unroll
            for (int nt = 0; nt < 2; nt++)
                ldmx4(b[nt], bB + (wn * 32 + nt * 16 + l15) * SRS + ks * 32 + lh * 16);
#pragma unroll
            for (int mi = 0; mi < 2; mi++)
#pragma unroll
                for (int nt = 0; nt < 2; nt++)
#pragma unroll
                    for (int s = 0; s < 2; s++)
                        mma_f16(acc[mi][nt * 2 + s], a[mi], b[nt][s], b[nt][s + 2]);
        }
    };

    load_stage(0, 0);
    const int nc = SEQ / 64;
    for (int c = 0; c < nc; c++) {
        if (c + 1 < nc) {
            load_stage((c + 1) & 1, (c + 1) * 64);
            cp_wait<1>();
        } else {
            cp_wait<0>();
        }
        __syncthreads();
        compute_stage(c & 1);
        __syncthreads();
    }

    int rb = m0 + wm * 32 + (lane >> 2);
    int cb = h * DH + wn * 32 + (lane & 3) * 2;
#pragma unroll
    for (int mi = 0; mi < 2; mi++)
#pragma unroll
        for (int nj = 0; nj < 4; nj++)
#pragma unroll
            for (int q = 0; q < 4; q++) {
                int m = rb + mi * 16 + (q >> 1) * 8;
                int n = cb + nj * 8 + (q & 1);
                __nv_bfloat16 hh, ll; split2(acc[mi][nj][q], hh, ll);
                long o = (long)m * DM + n;
                g_o1_hi[o] = hh; g_o1_lo[o] = ll;
            }
}

// ---------------- fused gather-shift + mask + softmax ------------------------
__global__ __launch_bounds__(256) void softmax_kernel(float* __restrict__ w,
                                                      const float* __restrict__ mask) {
    int s = blockIdx.x, h = blockIdx.y;
    long base = ((long)h * SEQ + s) * SEQ;
    const __half* hat = g_bds + (long)h * SS;
    __shared__ float red[8], red2[8];
    int tid = threadIdx.x;
    int lane = tid & 31, wid = tid >> 5;
    int j0 = tid * 8;

    // rel-shift gather geometry (two contiguous runs per row)
    long flat0 = (long)s * SEQ + (SEQ - 1);
    int sp0 = (int)(flat0 / (SEQ + 1));
    int jp0 = (int)(flat0 - (long)sp0 * (SEQ + 1));
    int jwrap = (SEQ + 1) - jp0;
    long base1 = (long)sp0 * SEQ + jp0;
    long base2 = (long)(sp0 + 1) * SEQ - jwrap;

    uint4 acr = *(const uint4*)(g_ac + base + j0);
    float4 mk0 = *(const float4*)(mask + (long)s * SEQ + j0);
    float4 mk1 = *(const float4*)(mask + (long)s * SEQ + j0 + 4);

    float vals[8];
    {
        const __half2* ah = (const __half2*)&acr;
#pragma unroll
        for (int i = 0; i < 4; i++) {
            float2 a2 = __half22float2(ah[i]);
            vals[2 * i]     = a2.x;
            vals[2 * i + 1] = a2.y;
        }
        const float* mka = (const float*)&mk0;
        const float* mkb = (const float*)&mk1;
#pragma unroll
        for (int i = 0; i < 4; i++) vals[i]     += mka[i];
#pragma unroll
        for (int i = 0; i < 4; i++) vals[4 + i] += mkb[i];

        if (j0 + 8 <= jwrap) {            // fully in run 1 (may include hole; fixed up below)
            const __half* p = hat + base1 + j0;
#pragma unroll
            for (int i = 0; i < 8; i++) vals[i] += __half2float(p[i]);
        } else if (j0 >= jwrap) {         // fully in run 2
            const __half* p = hat + base2 + j0;
#pragma unroll
            for (int i = 0; i < 8; i++) vals[i] += __half2float(p[i]);
        } else {                          // straddles the wrap (1 thread per row)
#pragma unroll
            for (int i = 0; i < 8; i++) {
                int j = j0 + i;
                if (j != s + 1)
                    vals[i] += __half2float(hat[(j < jwrap ? base1 : base2) + j]);
            }
        }
        // hole position j == s+1: restore value without bd
        int zp = s + 1 - j0;
        if (zp >= 0 && zp < 8) {
            float2 a2 = __half22float2(((const __half2*)&acr)[zp >> 1]);
            float m = (zp & 4) ? ((const float*)&mk1)[zp & 3] : ((const float*)&mk0)[zp];
            vals[zp] = ((zp & 1) ? a2.y : a2.x) + m;
        }
    }

    float vmax = -3.0e38f;
#pragma unroll
    for (int i = 0; i < 8; i++) vmax = fmaxf(vmax, vals[i]);
    vmax = wred_max(vmax);
    if (lane == 0) red[wid] = vmax;
    __syncthreads();
    vmax = red[0];
#pragma unroll
    for (int i = 1; i < 8; i++) vmax = fmaxf(vmax, red[i]);

    float sum = 0.0f;
#pragma unroll
    for (int i = 0; i < 8; i++) {
        vals[i] = __expf(vals[i] - vmax);
        sum += vals[i];
    }
    sum = wred_sum(sum);
    if (lane == 0) red2[wid] = sum;
    __syncthreads();
    sum = red2[0];
#pragma unroll
    for (int i = 1; i < 8; i++) sum += red2[i];
    float inv = 1.0f / sum;

    float4 o0 = make_float4(vals[0] * inv, vals[1] * inv, vals[2] * inv, vals[3] * inv);
    float4 o1 = make_float4(vals[4] * inv, vals[5] * inv, vals[6] * inv, vals[7] * inv);
    *(float4*)(w + base + j0)     = o0;
    *(float4*)(w + base + j0 + 4) = o1;

    uint2 h16;
    __half2* hp = (__half2*)&h16;
    hp[0] = __floats2half2_rn(o0.x, o0.y);
    hp[1] = __floats2half2_rn(o0.z, o0.w);
    *(uint2*)(g_w16 + base + j0) = h16;
    hp[0] = __floats2half2_rn(o1.x, o1.y);
    hp[1] = __floats2half2_rn(o1.z, o1.w);
    *(uint2*)(g_w16 + base + j0 + 4) = h16;

    if (tid == 0) atomicMax(&g_headmax[h], __float_as_int(inv));
}

__global__ void loss_kernel(float* __restrict__ out) {
    if (threadIdx.x == 0) {
        float s = 0.0f;
        for (int h = 0; h < NH; h++) s += __int_as_float(g_headmax[h]);
        out[(long)SEQ * DM + (long)NH * SS] = s / (float)NH;
    }
}

// ---------------- launcher ---------------------------------------------------
extern "C" void kernel_launch(void* const* d_in, const int* in_sizes, int n_in,
                              void* d_out, int out_size) {
    (void)in_sizes; (void)n_in; (void)out_size;
    const float* query = (const float*)d_in[0];
    const float* key   = (const float*)d_in[1];
    const float* value = (const float*)d_in[2];
    const float* mask  = (const float*)d_in[3];
    const float* Wq    = (const float*)d_in[4];
    const float* Wke   = (const float*)d_in[5];
    const float* Wkr   = (const float*)d_in[6];
    const float* Wv    = (const float*)d_in[7];
    const float* Wf    = (const float*)d_in[8];
    const float* up    = (const float*)d_in[9];
    const float* vp    = (const float*)d_in[10];

    float* out = (float*)d_out;
    float* w   = out + (long)SEQ * DM;

    constexpr int SMEM_V   = 2 * (2 * 128 * RS + 2 * 128 * RS);  // 81920
    constexpr int SMEM_F   = 2 * (2 * 128 * RS + 2 * 64 * RS);   // 61440
    constexpr int SMEM_P16 = 2 * P16_STAGE;                      // 73728
    constexpr int SMEM_E   = 2 * ESTAGE;                         // 55296
    constexpr int SMEM_S   = 3 * 128 * SRS;                      // 55296
    cudaFuncSetAttribute(projV,        cudaFuncAttributeMaxDynamicSharedMemorySize, SMEM_V);
    cudaFuncSetAttribute(final_k,      cudaFuncAttributeMaxDynamicSharedMemorySize, SMEM_F);
    cudaFuncSetAttribute(proj16,       cudaFuncAttributeMaxDynamicSharedMemorySize, SMEM_P16);
    cudaFuncSetAttribute(einsum16_k,   cudaFuncAttributeMaxDynamicSharedMemorySize, SMEM_E);
    cudaFuncSetAttribute(score_kernel, cudaFuncAttributeMaxDynamicSharedMemorySize, SMEM_S);

    // 1. merged relenc + input/weight converts (one launch)
    split_all<<<dim3(SEQ * DM / 1024, 1, 9), 256>>>(query, key, value, Wq, Wke, Wkr, Wv, Wf);

    // 2. projections: fp16 single-pass for q/k/rel, split-bf16 for V
    proj16<<<dim3(DM / 128, SEQ / 128, 3), 256, SMEM_P16>>>(up, vp);
    projV<<<dim3(DM / 128, SEQ / 128), 256, SMEM_V>>>();

    // 3. scores: stripe-persistent fp16 (y<16: A_C; y>=16: B_D_hat)
    score_kernel<<<dim3(SEQ / 128, 2 * NH), 256, SMEM_S>>>();

    // 4. fused gather-shift + mask + softmax; emits w (fp32) + w16 (fp16)
    softmax_kernel<<<dim3(SEQ, NH), 256>>>(w, mask);

    // 5. fp16 single-pass einsum -> o1 (bf16 hi/lo)
    einsum16_k<<<dim3(1, SEQ / 128, NH), 256, SMEM_E>>>();

    // 6. final projection + exact GELU (BN=64, 256 CTAs)
    final_k<<<dim3(DM / 64, SEQ / 128), 256, SMEM_F>>>(out);

    // 7. loss scalar
    loss_kernel<<<1, 1>>>(out);
}